// round 3
// baseline (speedup 1.0000x reference)
#include <cuda_runtime.h>
#include <math.h>
#include <stdint.h>

// ---------------- problem constants ----------------
#define BB 4
#define TT 784
#define GG 28
#define EE 768
#define HDIM 3072
#define NHEADS 12
#define DHEAD 64
#define NLAYERS 6
#define MM (BB*TT)        // 3136
#define MPAD 3200         // 25*128
#define NBH (BB*NHEADS)   // 48
#define SST 20            // smem row stride (words) for 16-float k-tiles

// ---------------- scratch ----------------
__device__ float g_xp_h[MPAD * EE];
__device__ float g_xp_l[MPAD * EE];
__device__ float g_h[MPAD * EE];
__device__ float g_y_h[MPAD * EE];
__device__ float g_y_l[MPAD * EE];
__device__ float g_qkv_h[MPAD * 3 * EE];
__device__ float g_qkv_l[MPAD * 3 * EE];
__device__ float g_scores[(size_t)NBH * TT * TT];
__device__ float g_scores_l[(size_t)NBH * TT * TT];
__device__ float g_o_h[MPAD * EE];
__device__ float g_o_l[MPAD * EE];
__device__ float g_mlp_h[MPAD * HDIM];
__device__ float g_mlp_l[MPAD * HDIM];
// pre-split weights
__device__ float g_iw_h[EE * EE];
__device__ float g_iw_l[EE * EE];
__device__ float g_inw_h[NLAYERS * 3 * EE * EE];
__device__ float g_inw_l[NLAYERS * 3 * EE * EE];
__device__ float g_outw_h[NLAYERS * EE * EE];
__device__ float g_outw_l[NLAYERS * EE * EE];
__device__ float g_w1_h[NLAYERS * HDIM * EE];
__device__ float g_w1_l[NLAYERS * HDIM * EE];
__device__ float g_w2_h[NLAYERS * EE * HDIM];
__device__ float g_w2_l[NLAYERS * EE * HDIM];

#define EPI_NONE 0
#define EPI_POS  1
#define EPI_RES  2
#define EPI_GELU 3

// ---------------- helpers ----------------
__device__ __forceinline__ float tf32r(float f) {
    uint32_t u;
    asm("cvt.rna.tf32.f32 %0, %1;" : "=r"(u) : "f"(f));
    return __uint_as_float(u);
}

__device__ __forceinline__ void mma_tf32(float d[4], const uint32_t a[4],
                                         uint32_t b0, uint32_t b1) {
    asm volatile(
        "mma.sync.aligned.m16n8k8.row.col.f32.tf32.tf32.f32 "
        "{%0,%1,%2,%3}, {%4,%5,%6,%7}, {%8,%9}, {%0,%1,%2,%3};"
        : "+f"(d[0]), "+f"(d[1]), "+f"(d[2]), "+f"(d[3])
        : "r"(a[0]), "r"(a[1]), "r"(a[2]), "r"(a[3]), "r"(b0), "r"(b1));
}

__device__ __forceinline__ void cpa16(uint32_t dst, const void* src) {
    asm volatile("cp.async.cg.shared.global [%0], [%1], 16;" :: "r"(dst), "l"(src));
}
__device__ __forceinline__ void cpa16z(uint32_t dst, const void* src, bool valid) {
    int sz = valid ? 16 : 0;
    asm volatile("cp.async.cg.shared.global [%0], [%1], 16, %2;"
                 :: "r"(dst), "l"(src), "r"(sz));
}
__device__ __forceinline__ void cp_commit() { asm volatile("cp.async.commit_group;"); }
__device__ __forceinline__ void cp_wait0() { asm volatile("cp.async.wait_group 0;"); }
__device__ __forceinline__ void cp_wait1() { asm volatile("cp.async.wait_group 1;"); }

// ---------------- weight split ----------------
__global__ void split_kernel(const float4* __restrict__ src, float4* __restrict__ hi,
                             float4* __restrict__ lo, int n4) {
    int i = blockIdx.x * 256 + threadIdx.x;
    if (i >= n4) return;
    float4 a = src[i];
    float4 h, l;
    h.x = tf32r(a.x); l.x = tf32r(a.x - h.x);
    h.y = tf32r(a.y); l.y = tf32r(a.y - h.y);
    h.z = tf32r(a.z); l.z = tf32r(a.z - h.z);
    h.w = tf32r(a.w); l.w = tf32r(a.w - h.w);
    hi[i] = h; lo[i] = l;
}

// ---------------- patch gather (split output) ----------------
__global__ void patch_gather(const float* __restrict__ x, float* __restrict__ xh,
                             float* __restrict__ xl) {
    int idx = blockIdx.x * 256 + threadIdx.x;
    if (idx >= MM * EE) return;
    int j = idx % EE;
    int m = idx / EE;
    int b = m / TT, t = m % TT;
    int gr = t / GG, gc = t % GG;
    int ch = j >> 8, pr = (j >> 4) & 15, pc = j & 15;
    float v = x[(((size_t)b * 448 + gr * 16 + pr) * 448 + (gc * 16 + pc)) * 3 + ch];
    float hv = tf32r(v);
    xh[idx] = hv;
    xl[idx] = tf32r(v - hv);
}

// ---------------- pre-split 3xTF32 GEMM, cp.async double-buffered ----------------
// C[M,N] = A @ W^T + bias (A,W given as hi/lo tf32 pairs). Tile 128x128.
__global__ __launch_bounds__(256, 2)
void gemm_pre(const float* __restrict__ Ah, const float* __restrict__ Al,
              const float* __restrict__ Wh, const float* __restrict__ Wl,
              const float* __restrict__ bias, const float* __restrict__ extra,
              float* __restrict__ C, float* __restrict__ Cl,
              int M, int N, int K, int epi, int split)
{
    extern __shared__ float sm[];
    int tid = threadIdx.x, warp = tid >> 5, lane = tid & 31;
    int r = lane >> 2, cq = lane & 3;
    int m0 = blockIdx.y * 128, n0 = blockIdx.x * 128;
    int wm = (warp & 3) * 32, wn = (warp >> 2) * 64;
    uint32_t smb = (uint32_t)__cvta_generic_to_shared(sm);

    int lrow = tid >> 1;
    int lh = tid & 1;                 // which 8-float half of the 16-float row
    const float* srcA_h = Ah + (size_t)(m0 + lrow) * K + lh * 8;
    const float* srcA_l = Al + (size_t)(m0 + lrow) * K + lh * 8;
    const float* srcW_h = Wh + (size_t)(n0 + lrow) * K + lh * 8;
    const float* srcW_l = Wl + (size_t)(n0 + lrow) * K + lh * 8;
    uint32_t dbase = smb + lrow * (SST * 4) + lh * 32;

    float acc[2][8][4] = {};
    const int KT = K >> 4;

    auto issue = [&](int st, int kc) {
        int k0 = kc << 4;
        uint32_t d = dbase + st * 40960;
        cpa16(d,             srcA_h + k0); cpa16(d + 16,             srcA_h + k0 + 4);
        cpa16(d + 10240,     srcA_l + k0); cpa16(d + 10240 + 16,     srcA_l + k0 + 4);
        cpa16(d + 20480,     srcW_h + k0); cpa16(d + 20480 + 16,     srcW_h + k0 + 4);
        cpa16(d + 30720,     srcW_l + k0); cpa16(d + 30720 + 16,     srcW_l + k0 + 4);
    };

    issue(0, 0); cp_commit();

    for (int kc = 0; kc < KT; kc++) {
        if (kc + 1 < KT) { issue((kc + 1) & 1, kc + 1); cp_commit(); cp_wait1(); }
        else cp_wait0();
        __syncthreads();

        const float* sAh = sm + (kc & 1) * 10240;
        const float* sAl = sAh + 2560;
        const float* sWh = sAh + 5120;
        const float* sWl = sAh + 7680;

        #pragma unroll
        for (int s = 0; s < 2; s++) {
            uint32_t ah[2][4], al[2][4];
            #pragma unroll
            for (int i2 = 0; i2 < 2; i2++) {
                int mr = wm + 16 * i2 + r;
                const float* p = sAh + mr * SST + 8 * s + 2 * cq;
                uint2 h0 = *reinterpret_cast<const uint2*>(p);
                uint2 h1 = *reinterpret_cast<const uint2*>(p + 8 * SST);
                ah[i2][0] = h0.x; ah[i2][1] = h1.x; ah[i2][2] = h0.y; ah[i2][3] = h1.y;
                const float* q = sAl + mr * SST + 8 * s + 2 * cq;
                uint2 l0 = *reinterpret_cast<const uint2*>(q);
                uint2 l1 = *reinterpret_cast<const uint2*>(q + 8 * SST);
                al[i2][0] = l0.x; al[i2][1] = l1.x; al[i2][2] = l0.y; al[i2][3] = l1.y;
            }
            #pragma unroll
            for (int j = 0; j < 8; j++) {
                int nr = wn + 8 * j + r;
                uint2 bh = *reinterpret_cast<const uint2*>(sWh + nr * SST + 8 * s + 2 * cq);
                uint2 bl = *reinterpret_cast<const uint2*>(sWl + nr * SST + 8 * s + 2 * cq);
                #pragma unroll
                for (int i2 = 0; i2 < 2; i2++) {
                    mma_tf32(acc[i2][j], ah[i2], bl.x, bl.y);
                    mma_tf32(acc[i2][j], al[i2], bh.x, bh.y);
                    mma_tf32(acc[i2][j], ah[i2], bh.x, bh.y);
                }
            }
        }
        __syncthreads();
    }

    #pragma unroll
    for (int i2 = 0; i2 < 2; i2++) {
        #pragma unroll
        for (int j = 0; j < 8; j++) {
            #pragma unroll
            for (int half = 0; half < 2; half++) {
                int m = m0 + wm + 16 * i2 + r + half * 8;
                #pragma unroll
                for (int e = 0; e < 2; e++) {
                    int n = n0 + wn + 8 * j + 2 * cq + e;
                    float v = acc[i2][j][half * 2 + e] + bias[n];
                    if (epi == EPI_POS)       v += extra[(size_t)(m % TT) * N + n];
                    else if (epi == EPI_RES)  v += extra[(size_t)m * N + n];
                    else if (epi == EPI_GELU) v = 0.5f * v * (1.0f + erff(v * 0.70710678118654752f));
                    if (split) {
                        float hv = tf32r(v);
                        C [(size_t)m * N + n] = hv;
                        Cl[(size_t)m * N + n] = tf32r(v - hv);
                    } else {
                        C[(size_t)m * N + n] = v;
                    }
                }
            }
        }
    }
}

// ---------------- attention scores via MMA: s = q.k/8 + mask ----------------
__global__ __launch_bounds__(256)
void attn_scores_mma(const float* __restrict__ qh, const float* __restrict__ ql,
                     float* __restrict__ scores)
{
    __shared__ float sQh[128 * SST], sQl[128 * SST], sKh[128 * SST], sKl[128 * SST];
    int bh = blockIdx.z, b = bh / NHEADS, h = bh % NHEADS;
    int q0 = blockIdx.y * 128, k0t = blockIdx.x * 128;
    int tid = threadIdx.x, warp = tid >> 5, lane = tid & 31;
    int r = lane >> 2, cq = lane & 3;
    int wm = (warp & 3) * 32, wn = (warp >> 2) * 64;

    int lrow = tid >> 1, lh = tid & 1;
    int qrow = q0 + lrow; bool qv = qrow < TT;
    int krow = k0t + lrow; bool kv = krow < TT;
    const float* srcQh = qh + ((size_t)(b * TT + (qv ? qrow : 0))) * (3 * EE) + h * DHEAD + lh * 8;
    const float* srcQl = ql + ((size_t)(b * TT + (qv ? qrow : 0))) * (3 * EE) + h * DHEAD + lh * 8;
    const float* srcKh = qh + ((size_t)(b * TT + (kv ? krow : 0))) * (3 * EE) + EE + h * DHEAD + lh * 8;
    const float* srcKl = ql + ((size_t)(b * TT + (kv ? krow : 0))) * (3 * EE) + EE + h * DHEAD + lh * 8;

    uint32_t dQh = (uint32_t)__cvta_generic_to_shared(sQh) + lrow * (SST * 4) + lh * 32;
    uint32_t dQl = (uint32_t)__cvta_generic_to_shared(sQl) + lrow * (SST * 4) + lh * 32;
    uint32_t dKh = (uint32_t)__cvta_generic_to_shared(sKh) + lrow * (SST * 4) + lh * 32;
    uint32_t dKl = (uint32_t)__cvta_generic_to_shared(sKl) + lrow * (SST * 4) + lh * 32;

    float acc[2][8][4] = {};

    for (int d0 = 0; d0 < DHEAD; d0 += 16) {
        cpa16z(dQh, srcQh + d0, qv); cpa16z(dQh + 16, srcQh + d0 + 4, qv);
        cpa16z(dQl, srcQl + d0, qv); cpa16z(dQl + 16, srcQl + d0 + 4, qv);
        cpa16z(dKh, srcKh + d0, kv); cpa16z(dKh + 16, srcKh + d0 + 4, kv);
        cpa16z(dKl, srcKl + d0, kv); cpa16z(dKl + 16, srcKl + d0 + 4, kv);
        cp_commit(); cp_wait0();
        __syncthreads();

        #pragma unroll
        for (int s = 0; s < 2; s++) {
            uint32_t ah[2][4], al[2][4];
            #pragma unroll
            for (int i2 = 0; i2 < 2; i2++) {
                int mr = wm + 16 * i2 + r;
                const float* p = sQh + mr * SST + 8 * s + 2 * cq;
                uint2 h0 = *reinterpret_cast<const uint2*>(p);
                uint2 h1 = *reinterpret_cast<const uint2*>(p + 8 * SST);
                ah[i2][0] = h0.x; ah[i2][1] = h1.x; ah[i2][2] = h0.y; ah[i2][3] = h1.y;
                const float* q = sQl + mr * SST + 8 * s + 2 * cq;
                uint2 l0 = *reinterpret_cast<const uint2*>(q);
                uint2 l1 = *reinterpret_cast<const uint2*>(q + 8 * SST);
                al[i2][0] = l0.x; al[i2][1] = l1.x; al[i2][2] = l0.y; al[i2][3] = l1.y;
            }
            #pragma unroll
            for (int j = 0; j < 8; j++) {
                int nr = wn + 8 * j + r;
                uint2 bh2 = *reinterpret_cast<const uint2*>(sKh + nr * SST + 8 * s + 2 * cq);
                uint2 bl2 = *reinterpret_cast<const uint2*>(sKl + nr * SST + 8 * s + 2 * cq);
                #pragma unroll
                for (int i2 = 0; i2 < 2; i2++) {
                    mma_tf32(acc[i2][j], ah[i2], bl2.x, bl2.y);
                    mma_tf32(acc[i2][j], al[i2], bh2.x, bh2.y);
                    mma_tf32(acc[i2][j], ah[i2], bh2.x, bh2.y);
                }
            }
        }
        __syncthreads();
    }

    #pragma unroll
    for (int i2 = 0; i2 < 2; i2++) {
        #pragma unroll
        for (int j = 0; j < 8; j++) {
            #pragma unroll
            for (int half = 0; half < 2; half++) {
                int q = q0 + wm + 16 * i2 + r + half * 8;
                if (q >= TT) continue;
                int rq = q / GG, cq2 = q - rq * GG;
                #pragma unroll
                for (int e = 0; e < 2; e++) {
                    int k = k0t + wn + 8 * j + 2 * cq + e;
                    if (k >= TT) continue;
                    int rk = k / GG, ck = k - rk * GG;
                    float s = acc[i2][j][half * 2 + e] * 0.125f;
                    if (abs(rq - rk) <= 4 && abs(cq2 - ck) <= 4) s = -1e30f;
                    scores[((size_t)bh * TT + q) * TT + k] = s;
                }
            }
        }
    }
}

// ---------------- row softmax (split output) ----------------
__global__ void softmax_rows(float* __restrict__ scores, float* __restrict__ scores_l)
{
    int q = blockIdx.x;
    int bh = blockIdx.y;
    float* p = scores + ((size_t)bh * TT + q) * TT;
    float* pl = scores_l + ((size_t)bh * TT + q) * TT;
    __shared__ float red[256];
    int tid = threadIdx.x;

    float mx = -1e30f;
    for (int i = tid; i < TT; i += 256) mx = fmaxf(mx, p[i]);
    red[tid] = mx; __syncthreads();
    for (int st = 128; st > 0; st >>= 1) {
        if (tid < st) red[tid] = fmaxf(red[tid], red[tid + st]);
        __syncthreads();
    }
    mx = red[0]; __syncthreads();

    float sum = 0.f;
    for (int i = tid; i < TT; i += 256) {
        float e = __expf(p[i] - mx);
        p[i] = e;
        sum += e;
    }
    red[tid] = sum; __syncthreads();
    for (int st = 128; st > 0; st >>= 1) {
        if (tid < st) red[tid] += red[tid + st];
        __syncthreads();
    }
    float inv = 1.0f / red[0];
    for (int i = tid; i < TT; i += 256) {
        float v = p[i] * inv;
        float hv = tf32r(v);
        p[i] = hv;
        pl[i] = tf32r(v - hv);
    }
}

// ---------------- o = P @ V via MMA (split output) ----------------
__global__ __launch_bounds__(256)
void attn_av_mma(const float* __restrict__ ph, const float* __restrict__ pl,
                 const float* __restrict__ vh, const float* __restrict__ vl,
                 float* __restrict__ oh, float* __restrict__ ol)
{
    __shared__ float sPh[128 * SST], sPl[128 * SST];
    __shared__ float sVh[16 * 68], sVl[16 * 68];
    int bh = blockIdx.y, b = bh / NHEADS, h = bh % NHEADS;
    int q0 = blockIdx.x * 128;
    int tid = threadIdx.x, warp = tid >> 5, lane = tid & 31;
    int r = lane >> 2, cq = lane & 3;
    int wm = warp * 16;

    int lrow = tid >> 1, lh2 = tid & 1;
    int qrow = q0 + lrow; bool qv = qrow < TT;
    size_t sbase = (size_t)bh * TT * TT + (size_t)(qv ? qrow : 0) * TT;
    const float* srcPh = ph + sbase + lh2 * 8;
    const float* srcPl = pl + sbase + lh2 * 8;
    int kr = tid >> 4, dc4 = (tid & 15) * 4;
    const float* srcVh = vh + (size_t)(b * TT) * (3 * EE) + 2 * EE + h * DHEAD + dc4;
    const float* srcVl = vl + (size_t)(b * TT) * (3 * EE) + 2 * EE + h * DHEAD + dc4;

    uint32_t dPh = (uint32_t)__cvta_generic_to_shared(sPh) + lrow * (SST * 4) + lh2 * 32;
    uint32_t dPl = (uint32_t)__cvta_generic_to_shared(sPl) + lrow * (SST * 4) + lh2 * 32;
    uint32_t dVh = (uint32_t)__cvta_generic_to_shared(sVh) + kr * 272 + (tid & 15) * 16;
    uint32_t dVl = (uint32_t)__cvta_generic_to_shared(sVl) + kr * 272 + (tid & 15) * 16;

    float acc[8][4] = {};

    for (int kc = 0; kc < TT / 16; kc++) {
        int k0 = kc * 16;
        cpa16z(dPh, srcPh + k0, qv); cpa16z(dPh + 16, srcPh + k0 + 4, qv);
        cpa16z(dPl, srcPl + k0, qv); cpa16z(dPl + 16, srcPl + k0 + 4, qv);
        cpa16(dVh, srcVh + (size_t)(k0 + kr) * (3 * EE));
        cpa16(dVl, srcVl + (size_t)(k0 + kr) * (3 * EE));
        cp_commit(); cp_wait0();
        __syncthreads();

        #pragma unroll
        for (int s = 0; s < 2; s++) {
            uint32_t ah[4], al[4];
            {
                int mr = wm + r;
                const float* p = sPh + mr * SST + 8 * s + 2 * cq;
                uint2 h0 = *reinterpret_cast<const uint2*>(p);
                uint2 h1 = *reinterpret_cast<const uint2*>(p + 8 * SST);
                ah[0] = h0.x; ah[1] = h1.x; ah[2] = h0.y; ah[3] = h1.y;
                const float* q = sPl + mr * SST + 8 * s + 2 * cq;
                uint2 l0 = *reinterpret_cast<const uint2*>(q);
                uint2 l1 = *reinterpret_cast<const uint2*>(q + 8 * SST);
                al[0] = l0.x; al[1] = l1.x; al[2] = l0.y; al[3] = l1.y;
            }
            int krow2 = 2 * cq + 8 * s;
            #pragma unroll
            for (int j = 0; j < 8; j++) {
                int nr = 8 * j + r;
                uint32_t bh0 = __float_as_uint(sVh[krow2 * 68 + nr]);
                uint32_t bh1 = __float_as_uint(sVh[(krow2 + 1) * 68 + nr]);
                uint32_t bl0 = __float_as_uint(sVl[krow2 * 68 + nr]);
                uint32_t bl1 = __float_as_uint(sVl[(krow2 + 1) * 68 + nr]);
                mma_tf32(acc[j], ah, bl0, bl1);
                mma_tf32(acc[j], al, bh0, bh1);
                mma_tf32(acc[j], ah, bh0, bh1);
            }
        }
        __syncthreads();
    }

    #pragma unroll
    for (int j = 0; j < 8; j++) {
        #pragma unroll
        for (int half = 0; half < 2; half++) {
            int q = q0 + wm + r + half * 8;
            if (q >= TT) continue;
            size_t m = (size_t)b * TT + q;
            #pragma unroll
            for (int e = 0; e < 2; e++) {
                int d = 8 * j + 2 * cq + e;
                float v = acc[j][half * 2 + e];
                float hv = tf32r(v);
                oh[m * EE + h * DHEAD + d] = hv;
                ol[m * EE + h * DHEAD + d] = tf32r(v - hv);
            }
        }
    }
}

// ---------------- layernorm (split output) ----------------
__global__ void ln_kernel(const float* __restrict__ x, const float* __restrict__ g,
                          const float* __restrict__ bp, float* __restrict__ yh,
                          float* __restrict__ yl)
{
    int m = blockIdx.x;
    const float* xr = x + (size_t)m * EE;
    __shared__ float red[256];
    int tid = threadIdx.x;

    float s = 0.f;
    for (int i = tid; i < EE; i += 256) s += xr[i];
    red[tid] = s; __syncthreads();
    for (int st = 128; st > 0; st >>= 1) { if (tid < st) red[tid] += red[tid + st]; __syncthreads(); }
    float mean = red[0] / EE; __syncthreads();

    float v = 0.f;
    for (int i = tid; i < EE; i += 256) { float d = xr[i] - mean; v += d * d; }
    red[tid] = v; __syncthreads();
    for (int st = 128; st > 0; st >>= 1) { if (tid < st) red[tid] += red[tid + st]; __syncthreads(); }
    float inv = rsqrtf(red[0] / EE + 1e-5f);

    for (int i = tid; i < EE; i += 256) {
        float val = (xr[i] - mean) * inv * g[i] + bp[i];
        float hv = tf32r(val);
        yh[(size_t)m * EE + i] = hv;
        yl[(size_t)m * EE + i] = tf32r(val - hv);
    }
}

// ---------------- head + flux ----------------
__global__ void head_kernel(const float* __restrict__ hbuf,
                            const float* __restrict__ lnw, const float* __restrict__ lnb,
                            const float* __restrict__ hw, const float* __restrict__ hb,
                            const float* __restrict__ mean_s, const float* __restrict__ std_s,
                            float* __restrict__ out)
{
    int m = blockIdx.x;
    const float* xr = hbuf + (size_t)m * EE;
    __shared__ float red[256];
    int tid = threadIdx.x;

    float s = 0.f;
    for (int i = tid; i < EE; i += 256) s += xr[i];
    red[tid] = s; __syncthreads();
    for (int st = 128; st > 0; st >>= 1) { if (tid < st) red[tid] += red[tid + st]; __syncthreads(); }
    float mean = red[0] / EE; __syncthreads();

    float v = 0.f;
    for (int i = tid; i < EE; i += 256) { float d = xr[i] - mean; v += d * d; }
    red[tid] = v; __syncthreads();
    for (int st = 128; st > 0; st >>= 1) { if (tid < st) red[tid] += red[tid + st]; __syncthreads(); }
    float inv = rsqrtf(red[0] / EE + 1e-5f); __syncthreads();

    float dot = 0.f;
    for (int i = tid; i < EE; i += 256)
        dot += ((xr[i] - mean) * inv * lnw[i] + lnb[i]) * hw[i];
    red[tid] = dot; __syncthreads();
    for (int st = 128; st > 0; st >>= 1) { if (tid < st) red[tid] += red[tid + st]; __syncthreads(); }

    if (tid == 0) {
        float logit = red[0] + hb[0];
        float lg = logit * std_s[0] + mean_s[0];
        float pf = exp10f(lg) - 1e-8f;
        pf = fminf(fmaxf(pf, 1e-15f), 1.0f);
        out[BB + m] = pf;
    }
}

__global__ void flux_reduce(float* __restrict__ out)
{
    int b = blockIdx.x;
    __shared__ float red[256];
    int tid = threadIdx.x;
    float s = 0.f;
    for (int i = tid; i < TT; i += 256) s += out[BB + b * TT + i];
    red[tid] = s; __syncthreads();
    for (int st = 128; st > 0; st >>= 1) { if (tid < st) red[tid] += red[tid + st]; __syncthreads(); }
    if (tid == 0) out[b] = fmaxf(red[0], 1e-15f);
}

// ---------------- launcher ----------------
extern "C" void kernel_launch(void* const* d_in, const int* in_sizes, int n_in,
                              void* d_out, int out_size)
{
    const float* x        = (const float*)d_in[0];
    const float* sxr_mean = (const float*)d_in[1];
    const float* sxr_std  = (const float*)d_in[2];
    const float* input_w  = (const float*)d_in[3];
    const float* input_b  = (const float*)d_in[4];
    const float* pos_emb  = (const float*)d_in[5];
    const float* ln1_w    = (const float*)d_in[6];
    const float* ln1_b    = (const float*)d_in[7];
    const float* in_w     = (const float*)d_in[8];
    const float* in_b     = (const float*)d_in[9];
    const float* out_w    = (const float*)d_in[10];
    const float* out_b    = (const float*)d_in[11];
    const float* ln2_w    = (const float*)d_in[12];
    const float* ln2_b    = (const float*)d_in[13];
    const float* w1       = (const float*)d_in[14];
    const float* b1       = (const float*)d_in[15];
    const float* w2       = (const float*)d_in[16];
    const float* b2       = (const float*)d_in[17];
    const float* head_lnw = (const float*)d_in[18];
    const float* head_lnb = (const float*)d_in[19];
    const float* head_w   = (const float*)d_in[20];
    const float* head_b   = (const float*)d_in[21];
    float* out = (float*)d_out;

    float *xph, *xpl, *h, *yh, *yl, *qkvh, *qkvl, *sc, *scl, *ohb, *olb, *mlph, *mlpl;
    float *iwh, *iwl, *inwh, *inwl, *outwh, *outwl, *w1h, *w1l, *w2h, *w2l;
    cudaGetSymbolAddress((void**)&xph,   g_xp_h);   cudaGetSymbolAddress((void**)&xpl,   g_xp_l);
    cudaGetSymbolAddress((void**)&h,     g_h);
    cudaGetSymbolAddress((void**)&yh,    g_y_h);    cudaGetSymbolAddress((void**)&yl,    g_y_l);
    cudaGetSymbolAddress((void**)&qkvh,  g_qkv_h);  cudaGetSymbolAddress((void**)&qkvl,  g_qkv_l);
    cudaGetSymbolAddress((void**)&sc,    g_scores); cudaGetSymbolAddress((void**)&scl,   g_scores_l);
    cudaGetSymbolAddress((void**)&ohb,   g_o_h);    cudaGetSymbolAddress((void**)&olb,   g_o_l);
    cudaGetSymbolAddress((void**)&mlph,  g_mlp_h);  cudaGetSymbolAddress((void**)&mlpl,  g_mlp_l);
    cudaGetSymbolAddress((void**)&iwh,   g_iw_h);   cudaGetSymbolAddress((void**)&iwl,   g_iw_l);
    cudaGetSymbolAddress((void**)&inwh,  g_inw_h);  cudaGetSymbolAddress((void**)&inwl,  g_inw_l);
    cudaGetSymbolAddress((void**)&outwh, g_outw_h); cudaGetSymbolAddress((void**)&outwl, g_outw_l);
    cudaGetSymbolAddress((void**)&w1h,   g_w1_h);   cudaGetSymbolAddress((void**)&w1l,   g_w1_l);
    cudaGetSymbolAddress((void**)&w2h,   g_w2_h);   cudaGetSymbolAddress((void**)&w2l,   g_w2_l);

    static bool attr_done = false;
    if (!attr_done) {
        cudaFuncSetAttribute(gemm_pre, cudaFuncAttributeMaxDynamicSharedMemorySize, 81920);
        attr_done = true;
    }

    // weight pre-split
    auto splitN = [&](const float* s, float* hi, float* lo, size_t n) {
        int n4 = (int)(n / 4);
        split_kernel<<<(n4 + 255) / 256, 256>>>((const float4*)s, (float4*)hi, (float4*)lo, n4);
    };
    splitN(input_w, iwh, iwl, (size_t)EE * EE);
    splitN(in_w,  inwh,  inwl,  (size_t)NLAYERS * 3 * EE * EE);
    splitN(out_w, outwh, outwl, (size_t)NLAYERS * EE * EE);
    splitN(w1,    w1h,   w1l,   (size_t)NLAYERS * HDIM * EE);
    splitN(w2,    w2h,   w2l,   (size_t)NLAYERS * EE * HDIM);

    patch_gather<<<(MM * EE + 255) / 256, 256>>>(x, xph, xpl);
    gemm_pre<<<dim3(EE / 128, MPAD / 128), 256, 81920>>>(
        xph, xpl, iwh, iwl, input_b, pos_emb, h, nullptr, MPAD, EE, EE, EPI_POS, 0);

    for (int l = 0; l < NLAYERS; l++) {
        const float* l1w = ln1_w + (size_t)l * EE;
        const float* l1b = ln1_b + (size_t)l * EE;
        const float* ib  = in_b  + (size_t)l * 3 * EE;
        const float* ob  = out_b + (size_t)l * EE;
        const float* l2w = ln2_w + (size_t)l * EE;
        const float* l2b = ln2_b + (size_t)l * EE;
        const float* B1  = b1 + (size_t)l * HDIM;
        const float* B2  = b2 + (size_t)l * EE;
        size_t inoff  = (size_t)l * 3 * EE * EE;
        size_t outoff = (size_t)l * EE * EE;
        size_t w1off  = (size_t)l * HDIM * EE;
        size_t w2off  = (size_t)l * EE * HDIM;

        ln_kernel<<<MM, 256>>>(h, l1w, l1b, yh, yl);
        gemm_pre<<<dim3(3 * EE / 128, MPAD / 128), 256, 81920>>>(
            yh, yl, inwh + inoff, inwl + inoff, ib, nullptr,
            qkvh, qkvl, MPAD, 3 * EE, EE, EPI_NONE, 1);
        attn_scores_mma<<<dim3(7, 7, NBH), 256>>>(qkvh, qkvl, sc);
        softmax_rows<<<dim3(TT, NBH), 256>>>(sc, scl);
        attn_av_mma<<<dim3(7, NBH), 256>>>(sc, scl, qkvh, qkvl, ohb, olb);
        gemm_pre<<<dim3(EE / 128, MPAD / 128), 256, 81920>>>(
            ohb, olb, outwh + outoff, outwl + outoff, ob, h,
            h, nullptr, MPAD, EE, EE, EPI_RES, 0);
        ln_kernel<<<MM, 256>>>(h, l2w, l2b, yh, yl);
        gemm_pre<<<dim3(HDIM / 128, MPAD / 128), 256, 81920>>>(
            yh, yl, w1h + w1off, w1l + w1off, B1, nullptr,
            mlph, mlpl, MPAD, HDIM, EE, EPI_GELU, 1);
        gemm_pre<<<dim3(EE / 128, MPAD / 128), 256, 81920>>>(
            mlph, mlpl, w2h + w2off, w2l + w2off, B2, h,
            h, nullptr, MPAD, EE, HDIM, EPI_RES, 0);
    }

    head_kernel<<<MM, 256>>>(h, head_lnw, head_lnb, head_w, head_b,
                             sxr_mean, sxr_std, out);
    flux_reduce<<<BB, 256>>>(out);
}

// round 4
// speedup vs baseline: 1.8797x; 1.8797x over previous
#include <cuda_runtime.h>
#include <cuda_fp16.h>
#include <math.h>
#include <stdint.h>

// ---------------- problem constants ----------------
#define BB 4
#define TT 784
#define GG 28
#define EE 768
#define HDIM 3072
#define NHEADS 12
#define DHEAD 64
#define NLAYERS 6
#define MM (BB*TT)        // 3136
#define MPAD 3200         // 25*128
#define NBH (BB*NHEADS)   // 48

// ---------------- scratch ----------------
__device__ __half g_xp_h[MPAD * EE];
__device__ __half g_xp_l[MPAD * EE];
__device__ float  g_h[MPAD * EE];
__device__ __half g_y_h[MPAD * EE];
__device__ __half g_y_l[MPAD * EE];
__device__ __half g_qkv_h[MPAD * 3 * EE];
__device__ __half g_qkv_l[MPAD * 3 * EE];
__device__ float  g_scores[(size_t)NBH * TT * TT];
__device__ __half g_p_h[(size_t)NBH * TT * TT];
__device__ __half g_p_l[(size_t)NBH * TT * TT];
__device__ __half g_o_h[MPAD * EE];
__device__ __half g_o_l[MPAD * EE];
__device__ __half g_mlp_h[MPAD * HDIM];
__device__ __half g_mlp_l[MPAD * HDIM];
// pre-split weights (fp16 hi/lo)
__device__ __half g_iw_h[EE * EE];
__device__ __half g_iw_l[EE * EE];
__device__ __half g_inw_h[NLAYERS * 3 * EE * EE];
__device__ __half g_inw_l[NLAYERS * 3 * EE * EE];
__device__ __half g_outw_h[NLAYERS * EE * EE];
__device__ __half g_outw_l[NLAYERS * EE * EE];
__device__ __half g_w1_h[NLAYERS * HDIM * EE];
__device__ __half g_w1_l[NLAYERS * HDIM * EE];
__device__ __half g_w2_h[NLAYERS * EE * HDIM];
__device__ __half g_w2_l[NLAYERS * EE * HDIM];

#define EPI_NONE 0
#define EPI_POS  1
#define EPI_RES  2
#define EPI_GELU 3

// ---------------- helpers ----------------
__device__ __forceinline__ void h_split(float v, __half& hi, __half& lo) {
    hi = __float2half_rn(v);
    lo = __float2half_rn(v - __half2float(hi));
}

__device__ __forceinline__ void mma_f16(float d[4],
                                        uint32_t a0, uint32_t a1, uint32_t a2, uint32_t a3,
                                        uint32_t b0, uint32_t b1) {
    asm volatile(
        "mma.sync.aligned.m16n8k16.row.col.f32.f16.f16.f32 "
        "{%0,%1,%2,%3}, {%4,%5,%6,%7}, {%8,%9}, {%0,%1,%2,%3};"
        : "+f"(d[0]), "+f"(d[1]), "+f"(d[2]), "+f"(d[3])
        : "r"(a0), "r"(a1), "r"(a2), "r"(a3), "r"(b0), "r"(b1));
}

__device__ __forceinline__ void cpa16(uint32_t dst, const void* src) {
    asm volatile("cp.async.cg.shared.global [%0], [%1], 16;" :: "r"(dst), "l"(src));
}
__device__ __forceinline__ void cpa16z(uint32_t dst, const void* src, bool valid) {
    int sz = valid ? 16 : 0;
    asm volatile("cp.async.cg.shared.global [%0], [%1], 16, %2;"
                 :: "r"(dst), "l"(src), "r"(sz));
}
__device__ __forceinline__ void cp_commit() { asm volatile("cp.async.commit_group;"); }
__device__ __forceinline__ void cp_wait0() { asm volatile("cp.async.wait_group 0;"); }
__device__ __forceinline__ void cp_wait1() { asm volatile("cp.async.wait_group 1;"); }

// ---------------- weight split (fp32 -> fp16 hi/lo) ----------------
__global__ void split_kernel(const float4* __restrict__ src, __half* __restrict__ hi,
                             __half* __restrict__ lo, int n4) {
    int i = blockIdx.x * 256 + threadIdx.x;
    if (i >= n4) return;
    float4 a = src[i];
    __half h0, l0, h1, l1, h2, l2, h3, l3;
    h_split(a.x, h0, l0); h_split(a.y, h1, l1);
    h_split(a.z, h2, l2); h_split(a.w, h3, l3);
    __half2* H = (__half2*)(hi + 4 * (size_t)i);
    __half2* L = (__half2*)(lo + 4 * (size_t)i);
    H[0] = __halves2half2(h0, h1); H[1] = __halves2half2(h2, h3);
    L[0] = __halves2half2(l0, l1); L[1] = __halves2half2(l2, l3);
}

// ---------------- patch gather (split output) ----------------
__global__ void patch_gather(const float* __restrict__ x, __half* __restrict__ xh,
                             __half* __restrict__ xl) {
    int idx = blockIdx.x * 256 + threadIdx.x;
    if (idx >= MM * EE) return;
    int j = idx % EE;
    int m = idx / EE;
    int b = m / TT, t = m % TT;
    int gr = t / GG, gc = t % GG;
    int ch = j >> 8, pr = (j >> 4) & 15, pc = j & 15;
    float v = x[(((size_t)b * 448 + gr * 16 + pr) * 448 + (gc * 16 + pc)) * 3 + ch];
    __half hv, lv;
    h_split(v, hv, lv);
    xh[idx] = hv; xl[idx] = lv;
}

// ---------------- split-FP16 3-pass GEMM, cp.async double-buffered ----------------
// C[M,N] = A @ W^T + bias. A,W given as fp16 hi/lo pairs. Block tile 128x128,
// k-tile 32 halves. Warp tile 32x64. Row stride 40 halves (conflict-free frag reads).
#define GST 40
__global__ __launch_bounds__(256, 2)
void gemm_h(const __half* __restrict__ Ah, const __half* __restrict__ Al,
            const __half* __restrict__ Wh, const __half* __restrict__ Wl,
            const float* __restrict__ bias, const float* __restrict__ extra,
            float* __restrict__ C, __half* __restrict__ Ch, __half* __restrict__ Cl,
            int M, int N, int K, int epi, int split)
{
    extern __shared__ __half smh[];
    int tid = threadIdx.x, warp = tid >> 5, lane = tid & 31;
    int r = lane >> 2, t2 = (lane & 3) * 2;
    int m0 = blockIdx.y * 128, n0 = blockIdx.x * 128;
    int wm = (warp & 3) * 32, wn = (warp >> 2) * 64;
    uint32_t smb = (uint32_t)__cvta_generic_to_shared(smh);

    int lrow = tid >> 1, lpart = tid & 1;       // 128 rows x 2 x 16-half parts
    const __half* srcA_h = Ah + (size_t)(m0 + lrow) * K + lpart * 16;
    const __half* srcA_l = Al + (size_t)(m0 + lrow) * K + lpart * 16;
    const __half* srcW_h = Wh + (size_t)(n0 + lrow) * K + lpart * 16;
    const __half* srcW_l = Wl + (size_t)(n0 + lrow) * K + lpart * 16;
    uint32_t dbase = smb + lrow * (GST * 2) + lpart * 32;

    float acc[2][8][4] = {};
    const int KT = K >> 5;

    auto issue = [&](int st, int kc) {
        int k0 = kc << 5;
        uint32_t d = dbase + st * 40960;
        cpa16(d,         srcA_h + k0); cpa16(d + 16,         srcA_h + k0 + 8);
        cpa16(d + 10240, srcA_l + k0); cpa16(d + 10240 + 16, srcA_l + k0 + 8);
        cpa16(d + 20480, srcW_h + k0); cpa16(d + 20480 + 16, srcW_h + k0 + 8);
        cpa16(d + 30720, srcW_l + k0); cpa16(d + 30720 + 16, srcW_l + k0 + 8);
    };

    issue(0, 0); cp_commit();

    for (int kc = 0; kc < KT; kc++) {
        if (kc + 1 < KT) { issue((kc + 1) & 1, kc + 1); cp_commit(); cp_wait1(); }
        else cp_wait0();
        __syncthreads();

        const __half* sAh = smh + (kc & 1) * 20480;
        const __half* sAl = sAh + 5120;
        const __half* sWh = sAh + 10240;
        const __half* sWl = sAh + 15360;

        #pragma unroll
        for (int s = 0; s < 2; s++) {
            int ks = s * 16;
            uint32_t ah[2][4], al[2][4];
            #pragma unroll
            for (int i2 = 0; i2 < 2; i2++) {
                const __half* pa = sAh + (wm + 16 * i2 + r) * GST + ks + t2;
                ah[i2][0] = *(const uint32_t*)pa;
                ah[i2][1] = *(const uint32_t*)(pa + 8 * GST);
                ah[i2][2] = *(const uint32_t*)(pa + 8);
                ah[i2][3] = *(const uint32_t*)(pa + 8 * GST + 8);
                const __half* pl = sAl + (wm + 16 * i2 + r) * GST + ks + t2;
                al[i2][0] = *(const uint32_t*)pl;
                al[i2][1] = *(const uint32_t*)(pl + 8 * GST);
                al[i2][2] = *(const uint32_t*)(pl + 8);
                al[i2][3] = *(const uint32_t*)(pl + 8 * GST + 8);
            }
            #pragma unroll
            for (int j = 0; j < 8; j++) {
                const __half* pw = sWh + (wn + 8 * j + r) * GST + ks + t2;
                uint32_t bh0 = *(const uint32_t*)pw;
                uint32_t bh1 = *(const uint32_t*)(pw + 8);
                const __half* pwl = sWl + (wn + 8 * j + r) * GST + ks + t2;
                uint32_t bl0 = *(const uint32_t*)pwl;
                uint32_t bl1 = *(const uint32_t*)(pwl + 8);
                #pragma unroll
                for (int i2 = 0; i2 < 2; i2++) {
                    mma_f16(acc[i2][j], ah[i2][0], ah[i2][1], ah[i2][2], ah[i2][3], bl0, bl1);
                    mma_f16(acc[i2][j], al[i2][0], al[i2][1], al[i2][2], al[i2][3], bh0, bh1);
                    mma_f16(acc[i2][j], ah[i2][0], ah[i2][1], ah[i2][2], ah[i2][3], bh0, bh1);
                }
            }
        }
        __syncthreads();
    }

    #pragma unroll
    for (int i2 = 0; i2 < 2; i2++) {
        #pragma unroll
        for (int j = 0; j < 8; j++) {
            #pragma unroll
            for (int half = 0; half < 2; half++) {
                int m = m0 + wm + 16 * i2 + r + half * 8;
                #pragma unroll
                for (int e = 0; e < 2; e++) {
                    int n = n0 + wn + 8 * j + t2 + e;
                    float v = acc[i2][j][half * 2 + e] + bias[n];
                    if (epi == EPI_POS)       v += extra[(size_t)(m % TT) * N + n];
                    else if (epi == EPI_RES)  v += extra[(size_t)m * N + n];
                    else if (epi == EPI_GELU) v = 0.5f * v * (1.0f + erff(v * 0.70710678118654752f));
                    if (split) {
                        __half hv, lv; h_split(v, hv, lv);
                        Ch[(size_t)m * N + n] = hv;
                        Cl[(size_t)m * N + n] = lv;
                    } else {
                        C[(size_t)m * N + n] = v;
                    }
                }
            }
        }
    }
}

// ---------------- attention scores via f16 MMA ----------------
#define AST 72
__global__ __launch_bounds__(256)
void attn_scores_h(const __half* __restrict__ qh, const __half* __restrict__ ql,
                   float* __restrict__ scores)
{
    extern __shared__ __half smh[];   // Qh,Ql,Kh,Kl each 128*72 halves
    __half* sQh = smh;
    __half* sQl = smh + 9216;
    __half* sKh = smh + 18432;
    __half* sKl = smh + 27648;

    int bh = blockIdx.z, b = bh / NHEADS, h = bh % NHEADS;
    int q0 = blockIdx.y * 128, k0t = blockIdx.x * 128;
    int tid = threadIdx.x, warp = tid >> 5, lane = tid & 31;
    int r = lane >> 2, t2 = (lane & 3) * 2;
    int wm = (warp & 3) * 32, wn = (warp >> 2) * 64;

    int lrow = tid >> 1, lpart = tid & 1;
    int qrow = q0 + lrow; bool qv = qrow < TT;
    int krow = k0t + lrow; bool kv = krow < TT;
    const __half* srcQh = qh + (size_t)(b * TT + (qv ? qrow : 0)) * (3 * EE) + h * DHEAD + lpart * 32;
    const __half* srcQl = ql + (size_t)(b * TT + (qv ? qrow : 0)) * (3 * EE) + h * DHEAD + lpart * 32;
    const __half* srcKh = qh + (size_t)(b * TT + (kv ? krow : 0)) * (3 * EE) + EE + h * DHEAD + lpart * 32;
    const __half* srcKl = ql + (size_t)(b * TT + (kv ? krow : 0)) * (3 * EE) + EE + h * DHEAD + lpart * 32;

    uint32_t smb = (uint32_t)__cvta_generic_to_shared(smh);
    uint32_t d0 = smb + lrow * (AST * 2) + lpart * 64;

    #pragma unroll
    for (int c = 0; c < 4; c++) {
        cpa16z(d0 + c * 16,         srcQh + c * 8, qv);
        cpa16z(d0 + 18432 + c * 16, srcQl + c * 8, qv);
        cpa16z(d0 + 36864 + c * 16, srcKh + c * 8, kv);
        cpa16z(d0 + 55296 + c * 16, srcKl + c * 8, kv);
    }
    cp_commit(); cp_wait0();
    __syncthreads();

    float acc[2][8][4] = {};
    #pragma unroll
    for (int s = 0; s < 4; s++) {
        int ks = s * 16;
        uint32_t ah[2][4], al[2][4];
        #pragma unroll
        for (int i2 = 0; i2 < 2; i2++) {
            const __half* pa = sQh + (wm + 16 * i2 + r) * AST + ks + t2;
            ah[i2][0] = *(const uint32_t*)pa;
            ah[i2][1] = *(const uint32_t*)(pa + 8 * AST);
            ah[i2][2] = *(const uint32_t*)(pa + 8);
            ah[i2][3] = *(const uint32_t*)(pa + 8 * AST + 8);
            const __half* pl = sQl + (wm + 16 * i2 + r) * AST + ks + t2;
            al[i2][0] = *(const uint32_t*)pl;
            al[i2][1] = *(const uint32_t*)(pl + 8 * AST);
            al[i2][2] = *(const uint32_t*)(pl + 8);
            al[i2][3] = *(const uint32_t*)(pl + 8 * AST + 8);
        }
        #pragma unroll
        for (int j = 0; j < 8; j++) {
            const __half* pw = sKh + (wn + 8 * j + r) * AST + ks + t2;
            uint32_t bh0 = *(const uint32_t*)pw;
            uint32_t bh1 = *(const uint32_t*)(pw + 8);
            const __half* pwl = sKl + (wn + 8 * j + r) * AST + ks + t2;
            uint32_t bl0 = *(const uint32_t*)pwl;
            uint32_t bl1 = *(const uint32_t*)(pwl + 8);
            #pragma unroll
            for (int i2 = 0; i2 < 2; i2++) {
                mma_f16(acc[i2][j], ah[i2][0], ah[i2][1], ah[i2][2], ah[i2][3], bl0, bl1);
                mma_f16(acc[i2][j], al[i2][0], al[i2][1], al[i2][2], al[i2][3], bh0, bh1);
                mma_f16(acc[i2][j], ah[i2][0], ah[i2][1], ah[i2][2], ah[i2][3], bh0, bh1);
            }
        }
    }

    #pragma unroll
    for (int i2 = 0; i2 < 2; i2++) {
        #pragma unroll
        for (int j = 0; j < 8; j++) {
            #pragma unroll
            for (int half = 0; half < 2; half++) {
                int q = q0 + wm + 16 * i2 + r + half * 8;
                if (q >= TT) continue;
                int rq = q / GG, cq2 = q - rq * GG;
                #pragma unroll
                for (int e = 0; e < 2; e++) {
                    int k = k0t + wn + 8 * j + t2 + e;
                    if (k >= TT) continue;
                    int rk = k / GG, ck = k - rk * GG;
                    float s = acc[i2][j][half * 2 + e] * 0.125f;
                    if (abs(rq - rk) <= 4 && abs(cq2 - ck) <= 4) s = -1e30f;
                    scores[((size_t)bh * TT + q) * TT + k] = s;
                }
            }
        }
    }
}

// ---------------- row softmax, register-cached, split-half output ----------------
__global__ void softmax_rows(const float* __restrict__ scores,
                             __half* __restrict__ ph, __half* __restrict__ pl)
{
    int q = blockIdx.x, bh = blockIdx.y;
    const float* p = scores + ((size_t)bh * TT + q) * TT;
    __half* oph = ph + ((size_t)bh * TT + q) * TT;
    __half* opl = pl + ((size_t)bh * TT + q) * TT;
    __shared__ float red[256];
    int tid = threadIdx.x;

    float v[4];
    float mx = -1e30f;
    #pragma unroll
    for (int i = 0; i < 4; i++) {
        int j = tid + i * 256;
        v[i] = (j < TT) ? p[j] : -1e30f;
        mx = fmaxf(mx, v[i]);
    }
    red[tid] = mx; __syncthreads();
    for (int st = 128; st > 0; st >>= 1) {
        if (tid < st) red[tid] = fmaxf(red[tid], red[tid + st]);
        __syncthreads();
    }
    mx = red[0]; __syncthreads();

    float sum = 0.f;
    #pragma unroll
    for (int i = 0; i < 4; i++) {
        v[i] = __expf(v[i] - mx);
        sum += v[i];
    }
    red[tid] = sum; __syncthreads();
    for (int st = 128; st > 0; st >>= 1) {
        if (tid < st) red[tid] += red[tid + st];
        __syncthreads();
    }
    float inv = 1.0f / red[0];
    #pragma unroll
    for (int i = 0; i < 4; i++) {
        int j = tid + i * 256;
        if (j < TT) {
            __half hv, lv; h_split(v[i] * inv, hv, lv);
            oph[j] = hv; opl[j] = lv;
        }
    }
}

// ---------------- o = P @ V via f16 MMA ----------------
#define PST 24
__global__ __launch_bounds__(256)
void attn_av_h(const __half* __restrict__ ph, const __half* __restrict__ pl,
               const __half* __restrict__ vh, const __half* __restrict__ vl,
               __half* __restrict__ oh, __half* __restrict__ ol)
{
    __shared__ __half sPh[128 * PST], sPl[128 * PST];
    __shared__ __half sVh[64 * PST], sVl[64 * PST];
    int bh = blockIdx.y, b = bh / NHEADS, h = bh % NHEADS;
    int q0 = blockIdx.x * 128;
    int tid = threadIdx.x, warp = tid >> 5, lane = tid & 31;
    int r = lane >> 2, t2 = (lane & 3) * 2;
    int wm = warp * 16;

    int lrow = tid >> 1, lpart = tid & 1;
    int qrow = q0 + lrow; bool qv = qrow < TT;
    size_t pbase = (size_t)bh * TT * TT + (size_t)(qv ? qrow : 0) * TT;
    const __half* srcPh = ph + pbase + lpart * 8;
    const __half* srcPl = pl + pbase + lpart * 8;

    int vd = tid & 63, vkq = tid >> 6;   // 4 k's per thread
    const __half* srcVh = vh + (size_t)(b * TT) * (3 * EE) + 2 * EE + h * DHEAD + vd;
    const __half* srcVl = vl + (size_t)(b * TT) * (3 * EE) + 2 * EE + h * DHEAD + vd;

    uint32_t smb = (uint32_t)__cvta_generic_to_shared(sPh);
    uint32_t smbL = (uint32_t)__cvta_generic_to_shared(sPl);
    uint32_t dPh = smb + lrow * (PST * 2) + lpart * 16;
    uint32_t dPl = smbL + lrow * (PST * 2) + lpart * 16;

    float acc[8][4] = {};

    for (int kc = 0; kc < TT / 16; kc++) {
        int k0 = kc * 16;
        cpa16z(dPh, srcPh + k0, qv);
        cpa16z(dPl, srcPl + k0, qv);
        cp_commit();
        #pragma unroll
        for (int i = 0; i < 4; i++) {
            int k = vkq * 4 + i;
            sVh[vd * PST + k] = srcVh[(size_t)(k0 + k) * (3 * EE)];
            sVl[vd * PST + k] = srcVl[(size_t)(k0 + k) * (3 * EE)];
        }
        cp_wait0();
        __syncthreads();

        uint32_t a0h, a1h, a2h, a3h, a0l, a1l, a2l, a3l;
        {
            const __half* pa = sPh + (wm + r) * PST + t2;
            a0h = *(const uint32_t*)pa;
            a1h = *(const uint32_t*)(pa + 8 * PST);
            a2h = *(const uint32_t*)(pa + 8);
            a3h = *(const uint32_t*)(pa + 8 * PST + 8);
            const __half* plp = sPl + (wm + r) * PST + t2;
            a0l = *(const uint32_t*)plp;
            a1l = *(const uint32_t*)(plp + 8 * PST);
            a2l = *(const uint32_t*)(plp + 8);
            a3l = *(const uint32_t*)(plp + 8 * PST + 8);
        }
        #pragma unroll
        for (int j = 0; j < 8; j++) {
            const __half* pv = sVh + (8 * j + r) * PST + t2;
            uint32_t bh0 = *(const uint32_t*)pv;
            uint32_t bh1 = *(const uint32_t*)(pv + 8);
            const __half* pvl = sVl + (8 * j + r) * PST + t2;
            uint32_t bl0 = *(const uint32_t*)pvl;
            uint32_t bl1 = *(const uint32_t*)(pvl + 8);
            mma_f16(acc[j], a0h, a1h, a2h, a3h, bl0, bl1);
            mma_f16(acc[j], a0l, a1l, a2l, a3l, bh0, bh1);
            mma_f16(acc[j], a0h, a1h, a2h, a3h, bh0, bh1);
        }
        __syncthreads();
    }

    #pragma unroll
    for (int j = 0; j < 8; j++) {
        #pragma unroll
        for (int half = 0; half < 2; half++) {
            int q = q0 + wm + r + half * 8;
            if (q >= TT) continue;
            size_t m = (size_t)b * TT + q;
            #pragma unroll
            for (int e = 0; e < 2; e++) {
                int d = 8 * j + t2 + e;
                __half hv, lv; h_split(acc[j][half * 2 + e], hv, lv);
                oh[m * EE + h * DHEAD + d] = hv;
                ol[m * EE + h * DHEAD + d] = lv;
            }
        }
    }
}

// ---------------- layernorm (split half output) ----------------
__global__ void ln_kernel(const float* __restrict__ x, const float* __restrict__ g,
                          const float* __restrict__ bp, __half* __restrict__ yh,
                          __half* __restrict__ yl)
{
    int m = blockIdx.x;
    const float* xr = x + (size_t)m * EE;
    __shared__ float red[256];
    int tid = threadIdx.x;

    float s = 0.f;
    for (int i = tid; i < EE; i += 256) s += xr[i];
    red[tid] = s; __syncthreads();
    for (int st = 128; st > 0; st >>= 1) { if (tid < st) red[tid] += red[tid + st]; __syncthreads(); }
    float mean = red[0] / EE; __syncthreads();

    float v = 0.f;
    for (int i = tid; i < EE; i += 256) { float d = xr[i] - mean; v += d * d; }
    red[tid] = v; __syncthreads();
    for (int st = 128; st > 0; st >>= 1) { if (tid < st) red[tid] += red[tid + st]; __syncthreads(); }
    float inv = rsqrtf(red[0] / EE + 1e-5f);

    for (int i = tid; i < EE; i += 256) {
        float val = (xr[i] - mean) * inv * g[i] + bp[i];
        __half hv, lv; h_split(val, hv, lv);
        yh[(size_t)m * EE + i] = hv;
        yl[(size_t)m * EE + i] = lv;
    }
}

// ---------------- head + flux ----------------
__global__ void head_kernel(const float* __restrict__ hbuf,
                            const float* __restrict__ lnw, const float* __restrict__ lnb,
                            const float* __restrict__ hw, const float* __restrict__ hb,
                            const float* __restrict__ mean_s, const float* __restrict__ std_s,
                            float* __restrict__ out)
{
    int m = blockIdx.x;
    const float* xr = hbuf + (size_t)m * EE;
    __shared__ float red[256];
    int tid = threadIdx.x;

    float s = 0.f;
    for (int i = tid; i < EE; i += 256) s += xr[i];
    red[tid] = s; __syncthreads();
    for (int st = 128; st > 0; st >>= 1) { if (tid < st) red[tid] += red[tid + st]; __syncthreads(); }
    float mean = red[0] / EE; __syncthreads();

    float v = 0.f;
    for (int i = tid; i < EE; i += 256) { float d = xr[i] - mean; v += d * d; }
    red[tid] = v; __syncthreads();
    for (int st = 128; st > 0; st >>= 1) { if (tid < st) red[tid] += red[tid + st]; __syncthreads(); }
    float inv = rsqrtf(red[0] / EE + 1e-5f); __syncthreads();

    float dot = 0.f;
    for (int i = tid; i < EE; i += 256)
        dot += ((xr[i] - mean) * inv * lnw[i] + lnb[i]) * hw[i];
    red[tid] = dot; __syncthreads();
    for (int st = 128; st > 0; st >>= 1) { if (tid < st) red[tid] += red[tid + st]; __syncthreads(); }

    if (tid == 0) {
        float logit = red[0] + hb[0];
        float lg = logit * std_s[0] + mean_s[0];
        float pf = exp10f(lg) - 1e-8f;
        pf = fminf(fmaxf(pf, 1e-15f), 1.0f);
        out[BB + m] = pf;
    }
}

__global__ void flux_reduce(float* __restrict__ out)
{
    int b = blockIdx.x;
    __shared__ float red[256];
    int tid = threadIdx.x;
    float s = 0.f;
    for (int i = tid; i < TT; i += 256) s += out[BB + b * TT + i];
    red[tid] = s; __syncthreads();
    for (int st = 128; st > 0; st >>= 1) { if (tid < st) red[tid] += red[tid + st]; __syncthreads(); }
    if (tid == 0) out[b] = fmaxf(red[0], 1e-15f);
}

// ---------------- launcher ----------------
extern "C" void kernel_launch(void* const* d_in, const int* in_sizes, int n_in,
                              void* d_out, int out_size)
{
    const float* x        = (const float*)d_in[0];
    const float* sxr_mean = (const float*)d_in[1];
    const float* sxr_std  = (const float*)d_in[2];
    const float* input_w  = (const float*)d_in[3];
    const float* input_b  = (const float*)d_in[4];
    const float* pos_emb  = (const float*)d_in[5];
    const float* ln1_w    = (const float*)d_in[6];
    const float* ln1_b    = (const float*)d_in[7];
    const float* in_w     = (const float*)d_in[8];
    const float* in_b     = (const float*)d_in[9];
    const float* out_w    = (const float*)d_in[10];
    const float* out_b    = (const float*)d_in[11];
    const float* ln2_w    = (const float*)d_in[12];
    const float* ln2_b    = (const float*)d_in[13];
    const float* w1       = (const float*)d_in[14];
    const float* b1       = (const float*)d_in[15];
    const float* w2       = (const float*)d_in[16];
    const float* b2       = (const float*)d_in[17];
    const float* head_lnw = (const float*)d_in[18];
    const float* head_lnb = (const float*)d_in[19];
    const float* head_w   = (const float*)d_in[20];
    const float* head_b   = (const float*)d_in[21];
    float* out = (float*)d_out;

    __half *xph, *xpl, *yh, *yl, *qkvh, *qkvl, *pph, *ppl, *ohb, *olb, *mlph, *mlpl;
    __half *iwh, *iwl, *inwh, *inwl, *outwh, *outwl, *w1h, *w1l, *w2h, *w2l;
    float *h, *sc;
    cudaGetSymbolAddress((void**)&xph,   g_xp_h);   cudaGetSymbolAddress((void**)&xpl,   g_xp_l);
    cudaGetSymbolAddress((void**)&h,     g_h);
    cudaGetSymbolAddress((void**)&yh,    g_y_h);    cudaGetSymbolAddress((void**)&yl,    g_y_l);
    cudaGetSymbolAddress((void**)&qkvh,  g_qkv_h);  cudaGetSymbolAddress((void**)&qkvl,  g_qkv_l);
    cudaGetSymbolAddress((void**)&sc,    g_scores);
    cudaGetSymbolAddress((void**)&pph,   g_p_h);    cudaGetSymbolAddress((void**)&ppl,   g_p_l);
    cudaGetSymbolAddress((void**)&ohb,   g_o_h);    cudaGetSymbolAddress((void**)&olb,   g_o_l);
    cudaGetSymbolAddress((void**)&mlph,  g_mlp_h);  cudaGetSymbolAddress((void**)&mlpl,  g_mlp_l);
    cudaGetSymbolAddress((void**)&iwh,   g_iw_h);   cudaGetSymbolAddress((void**)&iwl,   g_iw_l);
    cudaGetSymbolAddress((void**)&inwh,  g_inw_h);  cudaGetSymbolAddress((void**)&inwl,  g_inw_l);
    cudaGetSymbolAddress((void**)&outwh, g_outw_h); cudaGetSymbolAddress((void**)&outwl, g_outw_l);
    cudaGetSymbolAddress((void**)&w1h,   g_w1_h);   cudaGetSymbolAddress((void**)&w1l,   g_w1_l);
    cudaGetSymbolAddress((void**)&w2h,   g_w2_h);   cudaGetSymbolAddress((void**)&w2l,   g_w2_l);

    static bool attr_done = false;
    if (!attr_done) {
        cudaFuncSetAttribute(gemm_h, cudaFuncAttributeMaxDynamicSharedMemorySize, 81920);
        cudaFuncSetAttribute(attn_scores_h, cudaFuncAttributeMaxDynamicSharedMemorySize, 73728);
        attr_done = true;
    }

    auto splitN = [&](const float* s, __half* hi, __half* lo, size_t n) {
        int n4 = (int)(n / 4);
        split_kernel<<<(n4 + 255) / 256, 256>>>((const float4*)s, hi, lo, n4);
    };
    splitN(input_w, iwh, iwl, (size_t)EE * EE);
    splitN(in_w,  inwh,  inwl,  (size_t)NLAYERS * 3 * EE * EE);
    splitN(out_w, outwh, outwl, (size_t)NLAYERS * EE * EE);
    splitN(w1,    w1h,   w1l,   (size_t)NLAYERS * HDIM * EE);
    splitN(w2,    w2h,   w2l,   (size_t)NLAYERS * EE * HDIM);

    patch_gather<<<(MM * EE + 255) / 256, 256>>>(x, xph, xpl);
    gemm_h<<<dim3(EE / 128, MPAD / 128), 256, 81920>>>(
        xph, xpl, iwh, iwl, input_b, pos_emb, h, nullptr, nullptr,
        MPAD, EE, EE, EPI_POS, 0);

    for (int l = 0; l < NLAYERS; l++) {
        const float* l1w = ln1_w + (size_t)l * EE;
        const float* l1b = ln1_b + (size_t)l * EE;
        const float* ib  = in_b  + (size_t)l * 3 * EE;
        const float* ob  = out_b + (size_t)l * EE;
        const float* l2w = ln2_w + (size_t)l * EE;
        const float* l2b = ln2_b + (size_t)l * EE;
        const float* B1  = b1 + (size_t)l * HDIM;
        const float* B2  = b2 + (size_t)l * EE;
        size_t inoff  = (size_t)l * 3 * EE * EE;
        size_t outoff = (size_t)l * EE * EE;
        size_t w1off  = (size_t)l * HDIM * EE;
        size_t w2off  = (size_t)l * EE * HDIM;

        ln_kernel<<<MM, 256>>>(h, l1w, l1b, yh, yl);
        gemm_h<<<dim3(3 * EE / 128, MPAD / 128), 256, 81920>>>(
            yh, yl, inwh + inoff, inwl + inoff, ib, nullptr,
            nullptr, qkvh, qkvl, MPAD, 3 * EE, EE, EPI_NONE, 1);
        attn_scores_h<<<dim3(7, 7, NBH), 256, 73728>>>(qkvh, qkvl, sc);
        softmax_rows<<<dim3(TT, NBH), 256>>>(sc, pph, ppl);
        attn_av_h<<<dim3(7, NBH), 256>>>(pph, ppl, qkvh, qkvl, ohb, olb);
        gemm_h<<<dim3(EE / 128, MPAD / 128), 256, 81920>>>(
            ohb, olb, outwh + outoff, outwl + outoff, ob, h,
            h, nullptr, nullptr, MPAD, EE, EE, EPI_RES, 0);
        ln_kernel<<<MM, 256>>>(h, l2w, l2b, yh, yl);
        gemm_h<<<dim3(HDIM / 128, MPAD / 128), 256, 81920>>>(
            yh, yl, w1h + w1off, w1l + w1off, B1, nullptr,
            nullptr, mlph, mlpl, MPAD, HDIM, EE, EPI_GELU, 1);
        gemm_h<<<dim3(EE / 128, MPAD / 128), 256, 81920>>>(
            mlph, mlpl, w2h + w2off, w2l + w2off, B2, h,
            h, nullptr, nullptr, MPAD, EE, HDIM, EPI_RES, 0);
    }

    head_kernel<<<MM, 256>>>(h, head_lnw, head_lnb, head_w, head_b,
                             sxr_mean, sxr_std, out);
    flux_reduce<<<BB, 256>>>(out);
}

// round 6
// speedup vs baseline: 2.2991x; 1.2231x over previous
#include <cuda_runtime.h>
#include <cuda_fp16.h>
#include <math.h>
#include <stdint.h>

// ---------------- problem constants ----------------
#define BB 4
#define TT 784
#define GG 28
#define EE 768
#define HDIM 3072
#define NHEADS 12
#define DHEAD 64
#define NLAYERS 6
#define MM (BB*TT)        // 3136
#define MPAD 3200         // 25*128
#define NBH (BB*NHEADS)   // 48

// ---------------- scratch ----------------
__device__ __half g_xp_h[MPAD * EE];
__device__ __half g_xp_l[MPAD * EE];
__device__ float  g_h[MPAD * EE];
__device__ __half g_y_h[MPAD * EE];
__device__ __half g_y_l[MPAD * EE];
__device__ __half g_qkv_h[MPAD * 3 * EE];
__device__ __half g_qkv_l[MPAD * 3 * EE];
__device__ float  g_scores[(size_t)NBH * TT * TT];
__device__ __half g_p_h[(size_t)NBH * TT * TT];
__device__ __half g_p_l[(size_t)NBH * TT * TT];
__device__ __half g_o_h[MPAD * EE];
__device__ __half g_o_l[MPAD * EE];
__device__ __half g_mlp_h[MPAD * HDIM];
__device__ __half g_mlp_l[MPAD * HDIM];
// pre-converted weights (fp16 hi only; B-side stays fp16-rounded in 2-pass scheme)
__device__ __half g_iw_h[EE * EE];
__device__ __half g_inw_h[NLAYERS * 3 * EE * EE];
__device__ __half g_outw_h[NLAYERS * EE * EE];
__device__ __half g_w1_h[NLAYERS * HDIM * EE];
__device__ __half g_w2_h[NLAYERS * EE * HDIM];

#define EPI_NONE 0
#define EPI_POS  1
#define EPI_RES  2
#define EPI_GELU 3

// ---------------- helpers ----------------
__device__ __forceinline__ void h_split(float v, __half& hi, __half& lo) {
    hi = __float2half_rn(v);
    lo = __float2half_rn(v - __half2float(hi));
}

__device__ __forceinline__ void mma_f16(float d[4],
                                        uint32_t a0, uint32_t a1, uint32_t a2, uint32_t a3,
                                        uint32_t b0, uint32_t b1) {
    asm volatile(
        "mma.sync.aligned.m16n8k16.row.col.f32.f16.f16.f32 "
        "{%0,%1,%2,%3}, {%4,%5,%6,%7}, {%8,%9}, {%0,%1,%2,%3};"
        : "+f"(d[0]), "+f"(d[1]), "+f"(d[2]), "+f"(d[3])
        : "r"(a0), "r"(a1), "r"(a2), "r"(a3), "r"(b0), "r"(b1));
}

__device__ __forceinline__ void cpa16(uint32_t dst, const void* src) {
    asm volatile("cp.async.cg.shared.global [%0], [%1], 16;" :: "r"(dst), "l"(src));
}
__device__ __forceinline__ void cpa16z(uint32_t dst, const void* src, bool valid) {
    int sz = valid ? 16 : 0;
    asm volatile("cp.async.cg.shared.global [%0], [%1], 16, %2;"
                 :: "r"(dst), "l"(src), "r"(sz));
}
__device__ __forceinline__ void cp_commit() { asm volatile("cp.async.commit_group;"); }
__device__ __forceinline__ void cp_wait0() { asm volatile("cp.async.wait_group 0;"); }
__device__ __forceinline__ void cp_wait1() { asm volatile("cp.async.wait_group 1;"); }

// ---------------- weight convert (fp32 -> fp16 rn) ----------------
__global__ void conv_kernel(const float4* __restrict__ src, __half2* __restrict__ hi,
                            int n4) {
    int i = blockIdx.x * 256 + threadIdx.x;
    if (i >= n4) return;
    float4 a = src[i];
    hi[2 * (size_t)i]     = __halves2half2(__float2half_rn(a.x), __float2half_rn(a.y));
    hi[2 * (size_t)i + 1] = __halves2half2(__float2half_rn(a.z), __float2half_rn(a.w));
}

// ---------------- patch gather (split output) ----------------
__global__ void patch_gather(const float* __restrict__ x, __half* __restrict__ xh,
                             __half* __restrict__ xl) {
    int idx = blockIdx.x * 256 + threadIdx.x;
    if (idx >= MM * EE) return;
    int j = idx % EE;
    int m = idx / EE;
    int b = m / TT, t = m % TT;
    int gr = t / GG, gc = t % GG;
    int ch = j >> 8, pr = (j >> 4) & 15, pc = j & 15;
    float v = x[(((size_t)b * 448 + gr * 16 + pr) * 448 + (gc * 16 + pc)) * 3 + ch];
    __half hv, lv;
    h_split(v, hv, lv);
    xh[idx] = hv; xl[idx] = lv;
}

// ---------------- split-FP16 2-pass GEMM, cp.async double-buffered ----------------
// C[M,N] = (Ah+Al) @ Wh^T + bias. Block tile 128x128, k-tile 32 halves,
// warp tile 32x64. Row stride 40 halves.
#define GST 40
__global__ __launch_bounds__(256, 2)
void gemm_h(const __half* __restrict__ Ah, const __half* __restrict__ Al,
            const __half* __restrict__ Wh,
            const float* __restrict__ bias, const float* __restrict__ extra,
            float* __restrict__ C, __half* __restrict__ Ch, __half* __restrict__ Cl,
            int M, int N, int K, int epi, int split)
{
    extern __shared__ __half smh[];
    int tid = threadIdx.x, warp = tid >> 5, lane = tid & 31;
    int r = lane >> 2, t2 = (lane & 3) * 2;
    int m0 = blockIdx.y * 128, n0 = blockIdx.x * 128;
    int wm = (warp & 3) * 32, wn = (warp >> 2) * 64;
    uint32_t smb = (uint32_t)__cvta_generic_to_shared(smh);

    int lrow = tid >> 1, lpart = tid & 1;       // 128 rows x 2 x 16-half parts
    const __half* srcA_h = Ah + (size_t)(m0 + lrow) * K + lpart * 16;
    const __half* srcA_l = Al + (size_t)(m0 + lrow) * K + lpart * 16;
    const __half* srcW_h = Wh + (size_t)(n0 + lrow) * K + lpart * 16;
    uint32_t dbase = smb + lrow * (GST * 2) + lpart * 32;

    float acc[2][8][4] = {};
    const int KT = K >> 5;

    auto issue = [&](int st, int kc) {
        int k0 = kc << 5;
        uint32_t d = dbase + st * 30720;
        cpa16(d,         srcA_h + k0); cpa16(d + 16,         srcA_h + k0 + 8);
        cpa16(d + 10240, srcA_l + k0); cpa16(d + 10240 + 16, srcA_l + k0 + 8);
        cpa16(d + 20480, srcW_h + k0); cpa16(d + 20480 + 16, srcW_h + k0 + 8);
    };

    issue(0, 0); cp_commit();

    for (int kc = 0; kc < KT; kc++) {
        if (kc + 1 < KT) { issue((kc + 1) & 1, kc + 1); cp_commit(); cp_wait1(); }
        else cp_wait0();
        __syncthreads();

        const __half* sAh = smh + (kc & 1) * 15360;
        const __half* sAl = sAh + 5120;
        const __half* sWh = sAh + 10240;

        #pragma unroll
        for (int s = 0; s < 2; s++) {
            int ks = s * 16;
            uint32_t ah[2][4], al[2][4];
            #pragma unroll
            for (int i2 = 0; i2 < 2; i2++) {
                const __half* pa = sAh + (wm + 16 * i2 + r) * GST + ks + t2;
                ah[i2][0] = *(const uint32_t*)pa;
                ah[i2][1] = *(const uint32_t*)(pa + 8 * GST);
                ah[i2][2] = *(const uint32_t*)(pa + 8);
                ah[i2][3] = *(const uint32_t*)(pa + 8 * GST + 8);
                const __half* pl = sAl + (wm + 16 * i2 + r) * GST + ks + t2;
                al[i2][0] = *(const uint32_t*)pl;
                al[i2][1] = *(const uint32_t*)(pl + 8 * GST);
                al[i2][2] = *(const uint32_t*)(pl + 8);
                al[i2][3] = *(const uint32_t*)(pl + 8 * GST + 8);
            }
            #pragma unroll
            for (int j = 0; j < 8; j++) {
                const __half* pw = sWh + (wn + 8 * j + r) * GST + ks + t2;
                uint32_t bh0 = *(const uint32_t*)pw;
                uint32_t bh1 = *(const uint32_t*)(pw + 8);
                #pragma unroll
                for (int i2 = 0; i2 < 2; i2++) {
                    mma_f16(acc[i2][j], al[i2][0], al[i2][1], al[i2][2], al[i2][3], bh0, bh1);
                    mma_f16(acc[i2][j], ah[i2][0], ah[i2][1], ah[i2][2], ah[i2][3], bh0, bh1);
                }
            }
        }
        __syncthreads();
    }

    #pragma unroll
    for (int i2 = 0; i2 < 2; i2++) {
        #pragma unroll
        for (int j = 0; j < 8; j++) {
            #pragma unroll
            for (int half = 0; half < 2; half++) {
                int m = m0 + wm + 16 * i2 + r + half * 8;
                #pragma unroll
                for (int e = 0; e < 2; e++) {
                    int n = n0 + wn + 8 * j + t2 + e;
                    float v = acc[i2][j][half * 2 + e] + bias[n];
                    if (epi == EPI_POS)       v += extra[(size_t)(m % TT) * N + n];
                    else if (epi == EPI_RES)  v += extra[(size_t)m * N + n];
                    else if (epi == EPI_GELU) v = 0.5f * v * (1.0f + erff(v * 0.70710678118654752f));
                    if (split) {
                        __half hv, lv; h_split(v, hv, lv);
                        Ch[(size_t)m * N + n] = hv;
                        Cl[(size_t)m * N + n] = lv;
                    } else {
                        C[(size_t)m * N + n] = v;
                    }
                }
            }
        }
    }
}

// ---------------- attention scores via f16 MMA (2-pass: Qh.Kh + Ql.Kh) ----------------
#define AST 72
__global__ __launch_bounds__(256)
void attn_scores_h(const __half* __restrict__ qh, const __half* __restrict__ ql,
                   float* __restrict__ scores)
{
    extern __shared__ __half smh[];   // Qh,Ql,Kh each 128*72 halves
    __half* sQh = smh;
    __half* sQl = smh + 9216;
    __half* sKh = smh + 18432;

    int bh = blockIdx.z, b = bh / NHEADS, h = bh % NHEADS;
    int q0 = blockIdx.y * 128, k0t = blockIdx.x * 128;
    int tid = threadIdx.x, warp = tid >> 5, lane = tid & 31;
    int r = lane >> 2, t2 = (lane & 3) * 2;
    int wm = (warp & 3) * 32, wn = (warp >> 2) * 64;

    int lrow = tid >> 1, lpart = tid & 1;
    int qrow = q0 + lrow; bool qv = qrow < TT;
    int krow = k0t + lrow; bool kv = krow < TT;
    const __half* srcQh = qh + (size_t)(b * TT + (qv ? qrow : 0)) * (3 * EE) + h * DHEAD + lpart * 32;
    const __half* srcQl = ql + (size_t)(b * TT + (qv ? qrow : 0)) * (3 * EE) + h * DHEAD + lpart * 32;
    const __half* srcKh = qh + (size_t)(b * TT + (kv ? krow : 0)) * (3 * EE) + EE + h * DHEAD + lpart * 32;

    uint32_t smb = (uint32_t)__cvta_generic_to_shared(smh);
    uint32_t d0 = smb + lrow * (AST * 2) + lpart * 64;

    #pragma unroll
    for (int c = 0; c < 4; c++) {
        cpa16z(d0 + c * 16,         srcQh + c * 8, qv);
        cpa16z(d0 + 18432 + c * 16, srcQl + c * 8, qv);
        cpa16z(d0 + 36864 + c * 16, srcKh + c * 8, kv);
    }
    cp_commit(); cp_wait0();
    __syncthreads();

    float acc[2][8][4] = {};
    #pragma unroll
    for (int s = 0; s < 4; s++) {
        int ks = s * 16;
        uint32_t ah[2][4], al[2][4];
        #pragma unroll
        for (int i2 = 0; i2 < 2; i2++) {
            const __half* pa = sQh + (wm + 16 * i2 + r) * AST + ks + t2;
            ah[i2][0] = *(const uint32_t*)pa;
            ah[i2][1] = *(const uint32_t*)(pa + 8 * AST);
            ah[i2][2] = *(const uint32_t*)(pa + 8);
            ah[i2][3] = *(const uint32_t*)(pa + 8 * AST + 8);
            const __half* pl = sQl + (wm + 16 * i2 + r) * AST + ks + t2;
            al[i2][0] = *(const uint32_t*)pl;
            al[i2][1] = *(const uint32_t*)(pl + 8 * AST);
            al[i2][2] = *(const uint32_t*)(pl + 8);
            al[i2][3] = *(const uint32_t*)(pl + 8 * AST + 8);
        }
        #pragma unroll
        for (int j = 0; j < 8; j++) {
            const __half* pw = sKh + (wn + 8 * j + r) * AST + ks + t2;
            uint32_t bh0 = *(const uint32_t*)pw;
            uint32_t bh1 = *(const uint32_t*)(pw + 8);
            #pragma unroll
            for (int i2 = 0; i2 < 2; i2++) {
                mma_f16(acc[i2][j], al[i2][0], al[i2][1], al[i2][2], al[i2][3], bh0, bh1);
                mma_f16(acc[i2][j], ah[i2][0], ah[i2][1], ah[i2][2], ah[i2][3], bh0, bh1);
            }
        }
    }

    #pragma unroll
    for (int i2 = 0; i2 < 2; i2++) {
        #pragma unroll
        for (int j = 0; j < 8; j++) {
            #pragma unroll
            for (int half = 0; half < 2; half++) {
                int q = q0 + wm + 16 * i2 + r + half * 8;
                if (q >= TT) continue;
                int rq = q / GG, cq2 = q - rq * GG;
                #pragma unroll
                for (int e = 0; e < 2; e++) {
                    int k = k0t + wn + 8 * j + t2 + e;
                    if (k >= TT) continue;
                    int rk = k / GG, ck = k - rk * GG;
                    float s2 = acc[i2][j][half * 2 + e] * 0.125f;
                    if (abs(rq - rk) <= 4 && abs(cq2 - ck) <= 4) s2 = -1e30f;
                    scores[((size_t)bh * TT + q) * TT + k] = s2;
                }
            }
        }
    }
}

// ---------------- row softmax, register-cached, split-half output ----------------
__global__ void softmax_rows(const float* __restrict__ scores,
                             __half* __restrict__ ph, __half* __restrict__ pl)
{
    int q = blockIdx.x, bh = blockIdx.y;
    const float* p = scores + ((size_t)bh * TT + q) * TT;
    __half* oph = ph + ((size_t)bh * TT + q) * TT;
    __half* opl = pl + ((size_t)bh * TT + q) * TT;
    __shared__ float red[256];
    int tid = threadIdx.x;

    float v[4];
    float mx = -1e30f;
    #pragma unroll
    for (int i = 0; i < 4; i++) {
        int j = tid + i * 256;
        v[i] = (j < TT) ? p[j] : -1e30f;
        mx = fmaxf(mx, v[i]);
    }
    red[tid] = mx; __syncthreads();
    for (int st = 128; st > 0; st >>= 1) {
        if (tid < st) red[tid] = fmaxf(red[tid], red[tid + st]);
        __syncthreads();
    }
    mx = red[0]; __syncthreads();

    float sum = 0.f;
    #pragma unroll
    for (int i = 0; i < 4; i++) {
        v[i] = __expf(v[i] - mx);
        sum += v[i];
    }
    red[tid] = sum; __syncthreads();
    for (int st = 128; st > 0; st >>= 1) {
        if (tid < st) red[tid] += red[tid + st];
        __syncthreads();
    }
    float inv = 1.0f / red[0];
    #pragma unroll
    for (int i = 0; i < 4; i++) {
        int j = tid + i * 256;
        if (j < TT) {
            __half hv, lv; h_split(v[i] * inv, hv, lv);
            oph[j] = hv; opl[j] = lv;
        }
    }
}

// ---------------- o = P @ V via f16 MMA (2-pass: Ph.Vh + Pl.Vh) ----------------
#define PST 24
__global__ __launch_bounds__(256)
void attn_av_h(const __half* __restrict__ ph, const __half* __restrict__ pl,
               const __half* __restrict__ vh,
               __half* __restrict__ oh, __half* __restrict__ ol)
{
    __shared__ __half sPh[128 * PST], sPl[128 * PST];
    __shared__ __half sVh[64 * PST];
    int bh = blockIdx.y, b = bh / NHEADS, h = bh % NHEADS;
    int q0 = blockIdx.x * 128;
    int tid = threadIdx.x, warp = tid >> 5, lane = tid & 31;
    int r = lane >> 2, t2 = (lane & 3) * 2;
    int wm = warp * 16;

    int lrow = tid >> 1, lpart = tid & 1;
    int qrow = q0 + lrow; bool qv = qrow < TT;
    size_t pbase = (size_t)bh * TT * TT + (size_t)(qv ? qrow : 0) * TT;
    const __half* srcPh = ph + pbase + lpart * 8;
    const __half* srcPl = pl + pbase + lpart * 8;

    int vd = tid & 63, vkq = tid >> 6;   // 4 k's per thread
    const __half* srcVh = vh + (size_t)(b * TT) * (3 * EE) + 2 * EE + h * DHEAD + vd;

    uint32_t smb = (uint32_t)__cvta_generic_to_shared(sPh);
    uint32_t smbL = (uint32_t)__cvta_generic_to_shared(sPl);
    uint32_t dPh = smb + lrow * (PST * 2) + lpart * 16;
    uint32_t dPl = smbL + lrow * (PST * 2) + lpart * 16;

    float acc[8][4] = {};

    for (int kc = 0; kc < TT / 16; kc++) {
        int k0 = kc * 16;
        cpa16z(dPh, srcPh + k0, qv);
        cpa16z(dPl, srcPl + k0, qv);
        cp_commit();
        #pragma unroll
        for (int i = 0; i < 4; i++) {
            int k = vkq * 4 + i;
            sVh[vd * PST + k] = srcVh[(size_t)(k0 + k) * (3 * EE)];
        }
        cp_wait0();
        __syncthreads();

        uint32_t a0h, a1h, a2h, a3h, a0l, a1l, a2l, a3l;
        {
            const __half* pa = sPh + (wm + r) * PST + t2;
            a0h = *(const uint32_t*)pa;
            a1h = *(const uint32_t*)(pa + 8 * PST);
            a2h = *(const uint32_t*)(pa + 8);
            a3h = *(const uint32_t*)(pa + 8 * PST + 8);
            const __half* plp = sPl + (wm + r) * PST + t2;
            a0l = *(const uint32_t*)plp;
            a1l = *(const uint32_t*)(plp + 8 * PST);
            a2l = *(const uint32_t*)(plp + 8);
            a3l = *(const uint32_t*)(plp + 8 * PST + 8);
        }
        #pragma unroll
        for (int j = 0; j < 8; j++) {
            const __half* pv = sVh + (8 * j + r) * PST + t2;
            uint32_t bh0 = *(const uint32_t*)pv;
            uint32_t bh1 = *(const uint32_t*)(pv + 8);
            mma_f16(acc[j], a0l, a1l, a2l, a3l, bh0, bh1);
            mma_f16(acc[j], a0h, a1h, a2h, a3h, bh0, bh1);
        }
        __syncthreads();
    }

    #pragma unroll
    for (int j = 0; j < 8; j++) {
        #pragma unroll
        for (int half = 0; half < 2; half++) {
            int q = q0 + wm + r + half * 8;
            if (q >= TT) continue;
            size_t m = (size_t)b * TT + q;
            #pragma unroll
            for (int e = 0; e < 2; e++) {
                int d = 8 * j + t2 + e;
                __half hv, lv; h_split(acc[j][half * 2 + e], hv, lv);
                oh[m * EE + h * DHEAD + d] = hv;
                ol[m * EE + h * DHEAD + d] = lv;
            }
        }
    }
}

// ---------------- layernorm (split half output) ----------------
__global__ void ln_kernel(const float* __restrict__ x, const float* __restrict__ g,
                          const float* __restrict__ bp, __half* __restrict__ yh,
                          __half* __restrict__ yl)
{
    int m = blockIdx.x;
    const float* xr = x + (size_t)m * EE;
    __shared__ float red[256];
    int tid = threadIdx.x;

    float s = 0.f;
    for (int i = tid; i < EE; i += 256) s += xr[i];
    red[tid] = s; __syncthreads();
    for (int st = 128; st > 0; st >>= 1) { if (tid < st) red[tid] += red[tid + st]; __syncthreads(); }
    float mean = red[0] / EE; __syncthreads();

    float v = 0.f;
    for (int i = tid; i < EE; i += 256) { float d = xr[i] - mean; v += d * d; }
    red[tid] = v; __syncthreads();
    for (int st = 128; st > 0; st >>= 1) { if (tid < st) red[tid] += red[tid + st]; __syncthreads(); }
    float inv = rsqrtf(red[0] / EE + 1e-5f);

    for (int i = tid; i < EE; i += 256) {
        float val = (xr[i] - mean) * inv * g[i] + bp[i];
        __half hv, lv; h_split(val, hv, lv);
        yh[(size_t)m * EE + i] = hv;
        yl[(size_t)m * EE + i] = lv;
    }
}

// ---------------- head + flux ----------------
__global__ void head_kernel(const float* __restrict__ hbuf,
                            const float* __restrict__ lnw, const float* __restrict__ lnb,
                            const float* __restrict__ hw, const float* __restrict__ hb,
                            const float* __restrict__ mean_s, const float* __restrict__ std_s,
                            float* __restrict__ out)
{
    int m = blockIdx.x;
    const float* xr = hbuf + (size_t)m * EE;
    __shared__ float red[256];
    int tid = threadIdx.x;

    float s = 0.f;
    for (int i = tid; i < EE; i += 256) s += xr[i];
    red[tid] = s; __syncthreads();
    for (int st = 128; st > 0; st >>= 1) { if (tid < st) red[tid] += red[tid + st]; __syncthreads(); }
    float mean = red[0] / EE; __syncthreads();

    float v = 0.f;
    for (int i = tid; i < EE; i += 256) { float d = xr[i] - mean; v += d * d; }
    red[tid] = v; __syncthreads();
    for (int st = 128; st > 0; st >>= 1) { if (tid < st) red[tid] += red[tid + st]; __syncthreads(); }
    float inv = rsqrtf(red[0] / EE + 1e-5f); __syncthreads();

    float dot = 0.f;
    for (int i = tid; i < EE; i += 256)
        dot += ((xr[i] - mean) * inv * lnw[i] + lnb[i]) * hw[i];
    red[tid] = dot; __syncthreads();
    for (int st = 128; st > 0; st >>= 1) { if (tid < st) red[tid] += red[tid + st]; __syncthreads(); }

    if (tid == 0) {
        float logit = red[0] + hb[0];
        float lg = logit * std_s[0] + mean_s[0];
        float pf = exp10f(lg) - 1e-8f;
        pf = fminf(fmaxf(pf, 1e-15f), 1.0f);
        out[BB + m] = pf;
    }
}

__global__ void flux_reduce(float* __restrict__ out)
{
    int b = blockIdx.x;
    __shared__ float red[256];
    int tid = threadIdx.x;
    float s = 0.f;
    for (int i = tid; i < TT; i += 256) s += out[BB + b * TT + i];
    red[tid] = s; __syncthreads();
    for (int st = 128; st > 0; st >>= 1) { if (tid < st) red[tid] += red[tid + st]; __syncthreads(); }
    if (tid == 0) out[b] = fmaxf(red[0], 1e-15f);
}

// ---------------- launcher ----------------
extern "C" void kernel_launch(void* const* d_in, const int* in_sizes, int n_in,
                              void* d_out, int out_size)
{
    const float* x        = (const float*)d_in[0];
    const float* sxr_mean = (const float*)d_in[1];
    const float* sxr_std  = (const float*)d_in[2];
    const float* input_w  = (const float*)d_in[3];
    const float* input_b  = (const float*)d_in[4];
    const float* pos_emb  = (const float*)d_in[5];
    const float* ln1_w    = (const float*)d_in[6];
    const float* ln1_b    = (const float*)d_in[7];
    const float* in_w     = (const float*)d_in[8];
    const float* in_b     = (const float*)d_in[9];
    const float* out_w    = (const float*)d_in[10];
    const float* out_b    = (const float*)d_in[11];
    const float* ln2_w    = (const float*)d_in[12];
    const float* ln2_b    = (const float*)d_in[13];
    const float* w1       = (const float*)d_in[14];
    const float* b1       = (const float*)d_in[15];
    const float* w2       = (const float*)d_in[16];
    const float* b2       = (const float*)d_in[17];
    const float* head_lnw = (const float*)d_in[18];
    const float* head_lnb = (const float*)d_in[19];
    const float* head_w   = (const float*)d_in[20];
    const float* head_b   = (const float*)d_in[21];
    float* out = (float*)d_out;

    __half *xph, *xpl, *yh, *yl, *qkvh, *qkvl, *pph, *ppl, *ohb, *olb, *mlph, *mlpl;
    __half *iwh, *inwh, *outwh, *w1h, *w2h;
    float *h, *sc;
    cudaGetSymbolAddress((void**)&xph,   g_xp_h);   cudaGetSymbolAddress((void**)&xpl,   g_xp_l);
    cudaGetSymbolAddress((void**)&h,     g_h);
    cudaGetSymbolAddress((void**)&yh,    g_y_h);    cudaGetSymbolAddress((void**)&yl,    g_y_l);
    cudaGetSymbolAddress((void**)&qkvh,  g_qkv_h);  cudaGetSymbolAddress((void**)&qkvl,  g_qkv_l);
    cudaGetSymbolAddress((void**)&sc,    g_scores);
    cudaGetSymbolAddress((void**)&pph,   g_p_h);    cudaGetSymbolAddress((void**)&ppl,   g_p_l);
    cudaGetSymbolAddress((void**)&ohb,   g_o_h);    cudaGetSymbolAddress((void**)&olb,   g_o_l);
    cudaGetSymbolAddress((void**)&mlph,  g_mlp_h);  cudaGetSymbolAddress((void**)&mlpl,  g_mlp_l);
    cudaGetSymbolAddress((void**)&iwh,   g_iw_h);
    cudaGetSymbolAddress((void**)&inwh,  g_inw_h);
    cudaGetSymbolAddress((void**)&outwh, g_outw_h);
    cudaGetSymbolAddress((void**)&w1h,   g_w1_h);
    cudaGetSymbolAddress((void**)&w2h,   g_w2_h);

    static bool attr_done = false;
    if (!attr_done) {
        cudaFuncSetAttribute(gemm_h, cudaFuncAttributeMaxDynamicSharedMemorySize, 61440);
        cudaFuncSetAttribute(attn_scores_h, cudaFuncAttributeMaxDynamicSharedMemorySize, 55296);
        attr_done = true;
    }

    auto convN = [&](const float* s, __half* hi, size_t n) {
        int n4 = (int)(n / 4);
        conv_kernel<<<(n4 + 255) / 256, 256>>>((const float4*)s, (__half2*)hi, n4);
    };
    convN(input_w, iwh, (size_t)EE * EE);
    convN(in_w,  inwh,  (size_t)NLAYERS * 3 * EE * EE);
    convN(out_w, outwh, (size_t)NLAYERS * EE * EE);
    convN(w1,    w1h,   (size_t)NLAYERS * HDIM * EE);
    convN(w2,    w2h,   (size_t)NLAYERS * EE * HDIM);

    patch_gather<<<(MM * EE + 255) / 256, 256>>>(x, xph, xpl);
    gemm_h<<<dim3(EE / 128, MPAD / 128), 256, 61440>>>(
        xph, xpl, iwh, input_b, pos_emb, h, nullptr, nullptr,
        MPAD, EE, EE, EPI_POS, 0);

    for (int l = 0; l < NLAYERS; l++) {
        const float* l1w = ln1_w + (size_t)l * EE;
        const float* l1b = ln1_b + (size_t)l * EE;
        const float* ib  = in_b  + (size_t)l * 3 * EE;
        const float* ob  = out_b + (size_t)l * EE;
        const float* l2w = ln2_w + (size_t)l * EE;
        const float* l2b = ln2_b + (size_t)l * EE;
        const float* B1  = b1 + (size_t)l * HDIM;
        const float* B2  = b2 + (size_t)l * EE;
        size_t inoff  = (size_t)l * 3 * EE * EE;
        size_t outoff = (size_t)l * EE * EE;
        size_t w1off  = (size_t)l * HDIM * EE;
        size_t w2off  = (size_t)l * EE * HDIM;

        ln_kernel<<<MM, 256>>>(h, l1w, l1b, yh, yl);
        gemm_h<<<dim3(3 * EE / 128, MPAD / 128), 256, 61440>>>(
            yh, yl, inwh + inoff, ib, nullptr,
            nullptr, qkvh, qkvl, MPAD, 3 * EE, EE, EPI_NONE, 1);
        attn_scores_h<<<dim3(7, 7, NBH), 256, 55296>>>(qkvh, qkvl, sc);
        softmax_rows<<<dim3(TT, NBH), 256>>>(sc, pph, ppl);
        attn_av_h<<<dim3(7, NBH), 256>>>(pph, ppl, qkvh, ohb, olb);
        gemm_h<<<dim3(EE / 128, MPAD / 128), 256, 61440>>>(
            ohb, olb, outwh + outoff, ob, h,
            h, nullptr, nullptr, MPAD, EE, EE, EPI_RES, 0);
        ln_kernel<<<MM, 256>>>(h, l2w, l2b, yh, yl);
        gemm_h<<<dim3(HDIM / 128, MPAD / 128), 256, 61440>>>(
            yh, yl, w1h + w1off, B1, nullptr,
            nullptr, mlph, mlpl, MPAD, HDIM, EE, EPI_GELU, 1);
        gemm_h<<<dim3(EE / 128, MPAD / 128), 256, 61440>>>(
            mlph, mlpl, w2h + w2off, B2, h,
            h, nullptr, nullptr, MPAD, EE, HDIM, EPI_RES, 0);
    }

    head_kernel<<<MM, 256>>>(h, head_lnw, head_lnb, head_w, head_b,
                             sxr_mean, sxr_std, out);
    flux_reduce<<<BB, 256>>>(out);
}

// round 7
// speedup vs baseline: 2.6875x; 1.1690x over previous
#include <cuda_runtime.h>
#include <cuda_fp16.h>
#include <math.h>
#include <stdint.h>

// ---------------- problem constants ----------------
#define BB 4
#define TT 784
#define GG 28
#define EE 768
#define HDIM 3072
#define NHEADS 12
#define DHEAD 64
#define NLAYERS 6
#define MM (BB*TT)        // 3136
#define MPAD 3200         // 25*128
#define NBH (BB*NHEADS)   // 48

// ---------------- scratch ----------------
__device__ __half g_xp_h[MPAD * EE];
__device__ __half g_xp_l[MPAD * EE];
__device__ float  g_h[MPAD * EE];
__device__ __half g_y_h[MPAD * EE];
__device__ __half g_y_l[MPAD * EE];
__device__ __half g_qkv_h[MPAD * 3 * EE];
__device__ __half g_qkv_l[MPAD * 3 * EE];
__device__ __half g_o_h[MPAD * EE];
__device__ __half g_o_l[MPAD * EE];
__device__ __half g_mlp_h[MPAD * HDIM];
__device__ __half g_mlp_l[MPAD * HDIM];
// pre-converted weights (fp16; B-side of 2-pass scheme)
__device__ __half g_iw_h[EE * EE];
__device__ __half g_inw_h[NLAYERS * 3 * EE * EE];
__device__ __half g_outw_h[NLAYERS * EE * EE];
__device__ __half g_w1_h[NLAYERS * HDIM * EE];
__device__ __half g_w2_h[NLAYERS * EE * HDIM];

#define EPI_NONE 0
#define EPI_POS  1
#define EPI_RES  2
#define EPI_GELU 3

// ---------------- helpers ----------------
__device__ __forceinline__ void h_split(float v, __half& hi, __half& lo) {
    hi = __float2half_rn(v);
    lo = __float2half_rn(v - __half2float(hi));
}

__device__ __forceinline__ uint32_t packh2(__half a, __half b) {
    __half2 x = __halves2half2(a, b);
    return *reinterpret_cast<uint32_t*>(&x);
}

__device__ __forceinline__ void mma_f16(float d[4],
                                        uint32_t a0, uint32_t a1, uint32_t a2, uint32_t a3,
                                        uint32_t b0, uint32_t b1) {
    asm volatile(
        "mma.sync.aligned.m16n8k16.row.col.f32.f16.f16.f32 "
        "{%0,%1,%2,%3}, {%4,%5,%6,%7}, {%8,%9}, {%0,%1,%2,%3};"
        : "+f"(d[0]), "+f"(d[1]), "+f"(d[2]), "+f"(d[3])
        : "r"(a0), "r"(a1), "r"(a2), "r"(a3), "r"(b0), "r"(b1));
}

__device__ __forceinline__ void cpa16(uint32_t dst, const void* src) {
    asm volatile("cp.async.cg.shared.global [%0], [%1], 16;" :: "r"(dst), "l"(src));
}
__device__ __forceinline__ void cpa16z(uint32_t dst, const void* src, bool valid) {
    int sz = valid ? 16 : 0;
    asm volatile("cp.async.cg.shared.global [%0], [%1], 16, %2;"
                 :: "r"(dst), "l"(src), "r"(sz));
}
__device__ __forceinline__ void cp_commit() { asm volatile("cp.async.commit_group;"); }
__device__ __forceinline__ void cp_wait0() { asm volatile("cp.async.wait_group 0;"); }
__device__ __forceinline__ void cp_wait1() { asm volatile("cp.async.wait_group 1;"); }

// ---------------- weight convert (fp32 -> fp16 rn) ----------------
__global__ void conv_kernel(const float4* __restrict__ src, __half2* __restrict__ hi,
                            int n4) {
    int i = blockIdx.x * 256 + threadIdx.x;
    if (i >= n4) return;
    float4 a = src[i];
    hi[2 * (size_t)i]     = __halves2half2(__float2half_rn(a.x), __float2half_rn(a.y));
    hi[2 * (size_t)i + 1] = __halves2half2(__float2half_rn(a.z), __float2half_rn(a.w));
}

// ---------------- patch gather (split output) ----------------
__global__ void patch_gather(const float* __restrict__ x, __half* __restrict__ xh,
                             __half* __restrict__ xl) {
    int idx = blockIdx.x * 256 + threadIdx.x;
    if (idx >= MM * EE) return;
    int j = idx % EE;
    int m = idx / EE;
    int b = m / TT, t = m % TT;
    int gr = t / GG, gc = t % GG;
    int ch = j >> 8, pr = (j >> 4) & 15, pc = j & 15;
    float v = x[(((size_t)b * 448 + gr * 16 + pr) * 448 + (gc * 16 + pc)) * 3 + ch];
    __half hv, lv;
    h_split(v, hv, lv);
    xh[idx] = hv; xl[idx] = lv;
}

// ---------------- split-FP16 2-pass GEMM, cp.async double-buffered ----------------
#define GST 40
__global__ __launch_bounds__(256, 2)
void gemm_h(const __half* __restrict__ Ah, const __half* __restrict__ Al,
            const __half* __restrict__ Wh,
            const float* __restrict__ bias, const float* __restrict__ extra,
            float* __restrict__ C, __half* __restrict__ Ch, __half* __restrict__ Cl,
            int M, int N, int K, int epi, int split)
{
    extern __shared__ __half smh[];
    int tid = threadIdx.x, warp = tid >> 5, lane = tid & 31;
    int r = lane >> 2, t2 = (lane & 3) * 2;
    int m0 = blockIdx.y * 128, n0 = blockIdx.x * 128;
    int wm = (warp & 3) * 32, wn = (warp >> 2) * 64;
    uint32_t smb = (uint32_t)__cvta_generic_to_shared(smh);

    int lrow = tid >> 1, lpart = tid & 1;
    const __half* srcA_h = Ah + (size_t)(m0 + lrow) * K + lpart * 16;
    const __half* srcA_l = Al + (size_t)(m0 + lrow) * K + lpart * 16;
    const __half* srcW_h = Wh + (size_t)(n0 + lrow) * K + lpart * 16;
    uint32_t dbase = smb + lrow * (GST * 2) + lpart * 32;

    float acc[2][8][4] = {};
    const int KT = K >> 5;

    auto issue = [&](int st, int kc) {
        int k0 = kc << 5;
        uint32_t d = dbase + st * 30720;
        cpa16(d,         srcA_h + k0); cpa16(d + 16,         srcA_h + k0 + 8);
        cpa16(d + 10240, srcA_l + k0); cpa16(d + 10240 + 16, srcA_l + k0 + 8);
        cpa16(d + 20480, srcW_h + k0); cpa16(d + 20480 + 16, srcW_h + k0 + 8);
    };

    issue(0, 0); cp_commit();

    for (int kc = 0; kc < KT; kc++) {
        if (kc + 1 < KT) { issue((kc + 1) & 1, kc + 1); cp_commit(); cp_wait1(); }
        else cp_wait0();
        __syncthreads();

        const __half* sAh = smh + (kc & 1) * 15360;
        const __half* sAl = sAh + 5120;
        const __half* sWh = sAh + 10240;

        #pragma unroll
        for (int s = 0; s < 2; s++) {
            int ks = s * 16;
            uint32_t ah[2][4], al[2][4];
            #pragma unroll
            for (int i2 = 0; i2 < 2; i2++) {
                const __half* pa = sAh + (wm + 16 * i2 + r) * GST + ks + t2;
                ah[i2][0] = *(const uint32_t*)pa;
                ah[i2][1] = *(const uint32_t*)(pa + 8 * GST);
                ah[i2][2] = *(const uint32_t*)(pa + 8);
                ah[i2][3] = *(const uint32_t*)(pa + 8 * GST + 8);
                const __half* pl = sAl + (wm + 16 * i2 + r) * GST + ks + t2;
                al[i2][0] = *(const uint32_t*)pl;
                al[i2][1] = *(const uint32_t*)(pl + 8 * GST);
                al[i2][2] = *(const uint32_t*)(pl + 8);
                al[i2][3] = *(const uint32_t*)(pl + 8 * GST + 8);
            }
            #pragma unroll
            for (int j = 0; j < 8; j++) {
                const __half* pw = sWh + (wn + 8 * j + r) * GST + ks + t2;
                uint32_t bh0 = *(const uint32_t*)pw;
                uint32_t bh1 = *(const uint32_t*)(pw + 8);
                #pragma unroll
                for (int i2 = 0; i2 < 2; i2++) {
                    mma_f16(acc[i2][j], al[i2][0], al[i2][1], al[i2][2], al[i2][3], bh0, bh1);
                    mma_f16(acc[i2][j], ah[i2][0], ah[i2][1], ah[i2][2], ah[i2][3], bh0, bh1);
                }
            }
        }
        __syncthreads();
    }

    #pragma unroll
    for (int i2 = 0; i2 < 2; i2++) {
        #pragma unroll
        for (int j = 0; j < 8; j++) {
            #pragma unroll
            for (int half = 0; half < 2; half++) {
                int m = m0 + wm + 16 * i2 + r + half * 8;
                #pragma unroll
                for (int e = 0; e < 2; e++) {
                    int n = n0 + wn + 8 * j + t2 + e;
                    float v = acc[i2][j][half * 2 + e] + bias[n];
                    if (epi == EPI_POS)       v += extra[(size_t)(m % TT) * N + n];
                    else if (epi == EPI_RES)  v += extra[(size_t)m * N + n];
                    else if (epi == EPI_GELU) v = 0.5f * v * (1.0f + erff(v * 0.70710678118654752f));
                    if (split) {
                        __half hv, lv; h_split(v, hv, lv);
                        Ch[(size_t)m * N + n] = hv;
                        Cl[(size_t)m * N + n] = lv;
                    } else {
                        C[(size_t)m * N + n] = v;
                    }
                }
            }
        }
    }
}

// ---------------- fused flash attention ----------------
// One CTA per (128 q rows, head). Q hi/lo resident in smem; loop over 7
// k-blocks of 128: S = Q.K^T (2-pass), mask, online softmax in registers,
// P split hi/lo in registers, O += P.V (2-pass). No score traffic to HBM.
#define QST 72
#define VST 152
__global__ __launch_bounds__(256, 1)
void flash_attn(const __half* __restrict__ qh, const __half* __restrict__ ql,
                __half* __restrict__ oh, __half* __restrict__ ol)
{
    extern __shared__ __half sm[];
    __half* sQh = sm;                 // 128*72
    __half* sQl = sm + 9216;          // 128*72
    __half* sKh = sm + 18432;         // 128*72
    __half* sV  = sm + 27648;         // 64*152  [d][k]

    int bh = blockIdx.y, b = bh / NHEADS, h = bh % NHEADS;
    int q0 = blockIdx.x * 128;
    int tid = threadIdx.x, warp = tid >> 5, lane = tid & 31;
    int r = lane >> 2, t2 = (lane & 3) * 2;
    uint32_t smb = (uint32_t)__cvta_generic_to_shared(sm);

    int lrow = tid >> 1, lpart = tid & 1;

    // ---- load Q tile (once) ----
    {
        int qrow = q0 + lrow;
        bool qv = qrow < TT;
        const __half* sQg = qh + (size_t)(b * TT + (qv ? qrow : 0)) * (3 * EE) + h * DHEAD + lpart * 32;
        const __half* sQg2 = ql + (size_t)(b * TT + (qv ? qrow : 0)) * (3 * EE) + h * DHEAD + lpart * 32;
        uint32_t d0 = smb + lrow * (QST * 2) + lpart * 64;
        #pragma unroll
        for (int c = 0; c < 4; c++) {
            cpa16z(d0 + c * 16,         sQg  + c * 8, qv);
            cpa16z(d0 + 18432 + c * 16, sQg2 + c * 8, qv);
        }
    }
    cp_commit();

    // per-thread q rows (this warp owns rows 16*warp .. +16)
    int qi0 = q0 + 16 * warp + r;
    int qi1 = qi0 + 8;
    int rq0 = qi0 / GG, cq0 = qi0 - rq0 * GG;
    int rq1 = qi1 / GG, cq1 = qi1 - rq1 * GG;

    float m0 = -1e30f, m1 = -1e30f, l0 = 0.f, l1 = 0.f;
    float acc_o[8][4] = {};

    const __half* vbase = qh + (size_t)(b * TT) * (3 * EE) + 2 * EE + h * DHEAD;

    for (int kb = 0; kb < 7; kb++) {
        int k0 = kb * 128;
        __syncthreads();     // previous compute done before tiles overwritten

        // ---- load K tile ----
        {
            int krow = k0 + lrow;
            bool kv2 = krow < TT;
            const __half* sKg = qh + (size_t)(b * TT + (kv2 ? krow : 0)) * (3 * EE) + EE + h * DHEAD + lpart * 32;
            uint32_t dk = smb + 36864 + lrow * (QST * 2) + lpart * 64;
            #pragma unroll
            for (int c = 0; c < 4; c++) cpa16z(dk + c * 16, sKg + c * 8, kv2);
        }
        cp_commit();

        // ---- load V tile transposed [d][k] (scalar) ----
        {
            int vd = tid & 63;
            int kbase = (tid >> 6) * 32;
            #pragma unroll
            for (int i = 0; i < 32; i++) {
                int k = kbase + i;
                int tok = k0 + k;
                __half v = (tok < TT) ? vbase[(size_t)tok * (3 * EE) + vd] : __half(0.f);
                sV[vd * VST + k] = v;
            }
        }
        cp_wait0();
        __syncthreads();

        // ---- S = Q.K^T (2-pass), warp computes 16 x 128 ----
        float s[16][4] = {};
        #pragma unroll
        for (int ds = 0; ds < 4; ds++) {
            int ks = ds * 16;
            const __half* pa = sQh + (16 * warp + r) * QST + ks + t2;
            uint32_t ah0 = *(const uint32_t*)pa;
            uint32_t ah1 = *(const uint32_t*)(pa + 8 * QST);
            uint32_t ah2 = *(const uint32_t*)(pa + 8);
            uint32_t ah3 = *(const uint32_t*)(pa + 8 * QST + 8);
            const __half* pl = sQl + (16 * warp + r) * QST + ks + t2;
            uint32_t al0 = *(const uint32_t*)pl;
            uint32_t al1 = *(const uint32_t*)(pl + 8 * QST);
            uint32_t al2 = *(const uint32_t*)(pl + 8);
            uint32_t al3 = *(const uint32_t*)(pl + 8 * QST + 8);
            #pragma unroll
            for (int j = 0; j < 16; j++) {
                const __half* pk = sKh + (8 * j + r) * QST + ks + t2;
                uint32_t b0 = *(const uint32_t*)pk;
                uint32_t b1 = *(const uint32_t*)(pk + 8);
                mma_f16(s[j], al0, al1, al2, al3, b0, b1);
                mma_f16(s[j], ah0, ah1, ah2, ah3, b0, b1);
            }
        }

        // ---- mask + scale, block row max ----
        float bm0 = -1e30f, bm1 = -1e30f;
        #pragma unroll
        for (int j = 0; j < 16; j++) {
            #pragma unroll
            for (int e = 0; e < 2; e++) {
                int ki = k0 + 8 * j + t2 + e;
                int rk = ki / GG, ck = ki - rk * GG;
                bool oob = ki >= TT;
                float v0 = s[j][e] * 0.125f;
                if (oob || (abs(rq0 - rk) <= 4 && abs(cq0 - ck) <= 4)) v0 = -1e30f;
                s[j][e] = v0;
                bm0 = fmaxf(bm0, v0);
                float v1 = s[j][e + 2] * 0.125f;
                if (oob || (abs(rq1 - rk) <= 4 && abs(cq1 - ck) <= 4)) v1 = -1e30f;
                s[j][e + 2] = v1;
                bm1 = fmaxf(bm1, v1);
            }
        }
        bm0 = fmaxf(bm0, __shfl_xor_sync(0xFFFFFFFFu, bm0, 1));
        bm0 = fmaxf(bm0, __shfl_xor_sync(0xFFFFFFFFu, bm0, 2));
        bm1 = fmaxf(bm1, __shfl_xor_sync(0xFFFFFFFFu, bm1, 1));
        bm1 = fmaxf(bm1, __shfl_xor_sync(0xFFFFFFFFu, bm1, 2));

        float nm0 = fmaxf(m0, bm0), nm1 = fmaxf(m1, bm1);
        float sc0 = __expf(m0 - nm0), sc1 = __expf(m1 - nm1);
        m0 = nm0; m1 = nm1;

        float rs0 = 0.f, rs1 = 0.f;
        #pragma unroll
        for (int j = 0; j < 16; j++) {
            #pragma unroll
            for (int e = 0; e < 2; e++) {
                float p0 = __expf(s[j][e] - m0);
                s[j][e] = p0; rs0 += p0;
                float p1 = __expf(s[j][e + 2] - m1);
                s[j][e + 2] = p1; rs1 += p1;
            }
        }
        rs0 += __shfl_xor_sync(0xFFFFFFFFu, rs0, 1);
        rs0 += __shfl_xor_sync(0xFFFFFFFFu, rs0, 2);
        rs1 += __shfl_xor_sync(0xFFFFFFFFu, rs1, 1);
        rs1 += __shfl_xor_sync(0xFFFFFFFFu, rs1, 2);
        l0 = l0 * sc0 + rs0;
        l1 = l1 * sc1 + rs1;

        #pragma unroll
        for (int j2 = 0; j2 < 8; j2++) {
            acc_o[j2][0] *= sc0; acc_o[j2][1] *= sc0;
            acc_o[j2][2] *= sc1; acc_o[j2][3] *= sc1;
        }

        // ---- O += P.V (2-pass, P split hi/lo in registers) ----
        #pragma unroll
        for (int s2 = 0; s2 < 8; s2++) {
            __half h00, l00, h01, l01, h02, l02, h03, l03;
            __half h10, l10, h11, l11, h12, l12, h13, l13;
            h_split(s[2 * s2][0], h00, l00); h_split(s[2 * s2][1], h01, l01);
            h_split(s[2 * s2][2], h02, l02); h_split(s[2 * s2][3], h03, l03);
            h_split(s[2 * s2 + 1][0], h10, l10); h_split(s[2 * s2 + 1][1], h11, l11);
            h_split(s[2 * s2 + 1][2], h12, l12); h_split(s[2 * s2 + 1][3], h13, l13);
            uint32_t a0h = packh2(h00, h01), a1h = packh2(h02, h03);
            uint32_t a2h = packh2(h10, h11), a3h = packh2(h12, h13);
            uint32_t a0l = packh2(l00, l01), a1l = packh2(l02, l03);
            uint32_t a2l = packh2(l10, l11), a3l = packh2(l12, l13);
            #pragma unroll
            for (int j2 = 0; j2 < 8; j2++) {
                const __half* pv = sV + (8 * j2 + r) * VST + 16 * s2 + t2;
                uint32_t b0 = *(const uint32_t*)pv;
                uint32_t b1 = *(const uint32_t*)(pv + 8);
                mma_f16(acc_o[j2], a0l, a1l, a2l, a3l, b0, b1);
                mma_f16(acc_o[j2], a0h, a1h, a2h, a3h, b0, b1);
            }
        }
    }

    // ---- epilogue: O /= l, split write ----
    float il0 = 1.f / l0, il1 = 1.f / l1;
    #pragma unroll
    for (int j2 = 0; j2 < 8; j2++) {
        #pragma unroll
        for (int e = 0; e < 2; e++) {
            int d = 8 * j2 + t2 + e;
            if (qi0 < TT) {
                size_t mtk = (size_t)(b * TT + qi0) * EE + h * DHEAD + d;
                __half hv, lv; h_split(acc_o[j2][e] * il0, hv, lv);
                oh[mtk] = hv; ol[mtk] = lv;
            }
            if (qi1 < TT) {
                size_t mtk = (size_t)(b * TT + qi1) * EE + h * DHEAD + d;
                __half hv, lv; h_split(acc_o[j2][e + 2] * il1, hv, lv);
                oh[mtk] = hv; ol[mtk] = lv;
            }
        }
    }
}

// ---------------- layernorm (split half output) ----------------
__global__ void ln_kernel(const float* __restrict__ x, const float* __restrict__ g,
                          const float* __restrict__ bp, __half* __restrict__ yh,
                          __half* __restrict__ yl)
{
    int m = blockIdx.x;
    const float* xr = x + (size_t)m * EE;
    __shared__ float red[256];
    int tid = threadIdx.x;

    float s = 0.f;
    for (int i = tid; i < EE; i += 256) s += xr[i];
    red[tid] = s; __syncthreads();
    for (int st = 128; st > 0; st >>= 1) { if (tid < st) red[tid] += red[tid + st]; __syncthreads(); }
    float mean = red[0] / EE; __syncthreads();

    float v = 0.f;
    for (int i = tid; i < EE; i += 256) { float d = xr[i] - mean; v += d * d; }
    red[tid] = v; __syncthreads();
    for (int st = 128; st > 0; st >>= 1) { if (tid < st) red[tid] += red[tid + st]; __syncthreads(); }
    float inv = rsqrtf(red[0] / EE + 1e-5f);

    for (int i = tid; i < EE; i += 256) {
        float val = (xr[i] - mean) * inv * g[i] + bp[i];
        __half hv, lv; h_split(val, hv, lv);
        yh[(size_t)m * EE + i] = hv;
        yl[(size_t)m * EE + i] = lv;
    }
}

// ---------------- head + flux ----------------
__global__ void head_kernel(const float* __restrict__ hbuf,
                            const float* __restrict__ lnw, const float* __restrict__ lnb,
                            const float* __restrict__ hw, const float* __restrict__ hb,
                            const float* __restrict__ mean_s, const float* __restrict__ std_s,
                            float* __restrict__ out)
{
    int m = blockIdx.x;
    const float* xr = hbuf + (size_t)m * EE;
    __shared__ float red[256];
    int tid = threadIdx.x;

    float s = 0.f;
    for (int i = tid; i < EE; i += 256) s += xr[i];
    red[tid] = s; __syncthreads();
    for (int st = 128; st > 0; st >>= 1) { if (tid < st) red[tid] += red[tid + st]; __syncthreads(); }
    float mean = red[0] / EE; __syncthreads();

    float v = 0.f;
    for (int i = tid; i < EE; i += 256) { float d = xr[i] - mean; v += d * d; }
    red[tid] = v; __syncthreads();
    for (int st = 128; st > 0; st >>= 1) { if (tid < st) red[tid] += red[tid + st]; __syncthreads(); }
    float inv = rsqrtf(red[0] / EE + 1e-5f); __syncthreads();

    float dot = 0.f;
    for (int i = tid; i < EE; i += 256)
        dot += ((xr[i] - mean) * inv * lnw[i] + lnb[i]) * hw[i];
    red[tid] = dot; __syncthreads();
    for (int st = 128; st > 0; st >>= 1) { if (tid < st) red[tid] += red[tid + st]; __syncthreads(); }

    if (tid == 0) {
        float logit = red[0] + hb[0];
        float lg = logit * std_s[0] + mean_s[0];
        float pf = exp10f(lg) - 1e-8f;
        pf = fminf(fmaxf(pf, 1e-15f), 1.0f);
        out[BB + m] = pf;
    }
}

__global__ void flux_reduce(float* __restrict__ out)
{
    int b = blockIdx.x;
    __shared__ float red[256];
    int tid = threadIdx.x;
    float s = 0.f;
    for (int i = tid; i < TT; i += 256) s += out[BB + b * TT + i];
    red[tid] = s; __syncthreads();
    for (int st = 128; st > 0; st >>= 1) { if (tid < st) red[tid] += red[tid + st]; __syncthreads(); }
    if (tid == 0) out[b] = fmaxf(red[0], 1e-15f);
}

// ---------------- launcher ----------------
extern "C" void kernel_launch(void* const* d_in, const int* in_sizes, int n_in,
                              void* d_out, int out_size)
{
    const float* x        = (const float*)d_in[0];
    const float* sxr_mean = (const float*)d_in[1];
    const float* sxr_std  = (const float*)d_in[2];
    const float* input_w  = (const float*)d_in[3];
    const float* input_b  = (const float*)d_in[4];
    const float* pos_emb  = (const float*)d_in[5];
    const float* ln1_w    = (const float*)d_in[6];
    const float* ln1_b    = (const float*)d_in[7];
    const float* in_w     = (const float*)d_in[8];
    const float* in_b     = (const float*)d_in[9];
    const float* out_w    = (const float*)d_in[10];
    const float* out_b    = (const float*)d_in[11];
    const float* ln2_w    = (const float*)d_in[12];
    const float* ln2_b    = (const float*)d_in[13];
    const float* w1       = (const float*)d_in[14];
    const float* b1       = (const float*)d_in[15];
    const float* w2       = (const float*)d_in[16];
    const float* b2       = (const float*)d_in[17];
    const float* head_lnw = (const float*)d_in[18];
    const float* head_lnb = (const float*)d_in[19];
    const float* head_w   = (const float*)d_in[20];
    const float* head_b   = (const float*)d_in[21];
    float* out = (float*)d_out;

    __half *xph, *xpl, *yh, *yl, *qkvh, *qkvl, *ohb, *olb, *mlph, *mlpl;
    __half *iwh, *inwh, *outwh, *w1h, *w2h;
    float *h;
    cudaGetSymbolAddress((void**)&xph,   g_xp_h);   cudaGetSymbolAddress((void**)&xpl,   g_xp_l);
    cudaGetSymbolAddress((void**)&h,     g_h);
    cudaGetSymbolAddress((void**)&yh,    g_y_h);    cudaGetSymbolAddress((void**)&yl,    g_y_l);
    cudaGetSymbolAddress((void**)&qkvh,  g_qkv_h);  cudaGetSymbolAddress((void**)&qkvl,  g_qkv_l);
    cudaGetSymbolAddress((void**)&ohb,   g_o_h);    cudaGetSymbolAddress((void**)&olb,   g_o_l);
    cudaGetSymbolAddress((void**)&mlph,  g_mlp_h);  cudaGetSymbolAddress((void**)&mlpl,  g_mlp_l);
    cudaGetSymbolAddress((void**)&iwh,   g_iw_h);
    cudaGetSymbolAddress((void**)&inwh,  g_inw_h);
    cudaGetSymbolAddress((void**)&outwh, g_outw_h);
    cudaGetSymbolAddress((void**)&w1h,   g_w1_h);
    cudaGetSymbolAddress((void**)&w2h,   g_w2_h);

    static bool attr_done = false;
    if (!attr_done) {
        cudaFuncSetAttribute(gemm_h, cudaFuncAttributeMaxDynamicSharedMemorySize, 61440);
        cudaFuncSetAttribute(flash_attn, cudaFuncAttributeMaxDynamicSharedMemorySize, 74752);
        attr_done = true;
    }

    auto convN = [&](const float* s, __half* hi, size_t n) {
        int n4 = (int)(n / 4);
        conv_kernel<<<(n4 + 255) / 256, 256>>>((const float4*)s, (__half2*)hi, n4);
    };
    convN(input_w, iwh, (size_t)EE * EE);
    convN(in_w,  inwh,  (size_t)NLAYERS * 3 * EE * EE);
    convN(out_w, outwh, (size_t)NLAYERS * EE * EE);
    convN(w1,    w1h,   (size_t)NLAYERS * HDIM * EE);
    convN(w2,    w2h,   (size_t)NLAYERS * EE * HDIM);

    patch_gather<<<(MM * EE + 255) / 256, 256>>>(x, xph, xpl);
    gemm_h<<<dim3(EE / 128, MPAD / 128), 256, 61440>>>(
        xph, xpl, iwh, input_b, pos_emb, h, nullptr, nullptr,
        MPAD, EE, EE, EPI_POS, 0);

    for (int l = 0; l < NLAYERS; l++) {
        const float* l1w = ln1_w + (size_t)l * EE;
        const float* l1b = ln1_b + (size_t)l * EE;
        const float* ib  = in_b  + (size_t)l * 3 * EE;
        const float* ob  = out_b + (size_t)l * EE;
        const float* l2w = ln2_w + (size_t)l * EE;
        const float* l2b = ln2_b + (size_t)l * EE;
        const float* B1  = b1 + (size_t)l * HDIM;
        const float* B2  = b2 + (size_t)l * EE;
        size_t inoff  = (size_t)l * 3 * EE * EE;
        size_t outoff = (size_t)l * EE * EE;
        size_t w1off  = (size_t)l * HDIM * EE;
        size_t w2off  = (size_t)l * EE * HDIM;

        ln_kernel<<<MM, 256>>>(h, l1w, l1b, yh, yl);
        gemm_h<<<dim3(3 * EE / 128, MPAD / 128), 256, 61440>>>(
            yh, yl, inwh + inoff, ib, nullptr,
            nullptr, qkvh, qkvl, MPAD, 3 * EE, EE, EPI_NONE, 1);
        flash_attn<<<dim3(7, NBH), 256, 74752>>>(qkvh, qkvl, ohb, olb);
        gemm_h<<<dim3(EE / 128, MPAD / 128), 256, 61440>>>(
            ohb, olb, outwh + outoff, ob, h,
            h, nullptr, nullptr, MPAD, EE, EE, EPI_RES, 0);
        ln_kernel<<<MM, 256>>>(h, l2w, l2b, yh, yl);
        gemm_h<<<dim3(HDIM / 128, MPAD / 128), 256, 61440>>>(
            yh, yl, w1h + w1off, B1, nullptr,
            nullptr, mlph, mlpl, MPAD, HDIM, EE, EPI_GELU, 1);
        gemm_h<<<dim3(EE / 128, MPAD / 128), 256, 61440>>>(
            mlph, mlpl, w2h + w2off, B2, h,
            h, nullptr, nullptr, MPAD, EE, HDIM, EPI_RES, 0);
    }

    head_kernel<<<MM, 256>>>(h, head_lnw, head_lnb, head_w, head_b,
                             sxr_mean, sxr_std, out);
    flux_reduce<<<BB, 256>>>(out);
}